// round 6
// baseline (speedup 1.0000x reference)
#include <cuda_runtime.h>
#include <math.h>
#include <stdint.h>

#define BATCH   16
#define CH      512
#define HW_     1024
#define NGROUPS 8
#define CG      (CH/NGROUPS)
#define NH      8
#define HD      64
#define EPS_    1e-5f
#define SCALE_  0.125f

// Scratch (allocation-free)
__device__ float g_xn [BATCH*CH*HW_];
__device__ float g_qkv[(size_t)BATCH*3*CH*HW_];
__device__ float g_att[BATCH*CH*HW_];

__device__ __forceinline__ uint32_t f2tf32(float f) {
    uint32_t u;
    asm("cvt.rna.tf32.f32 %0, %1;" : "=r"(u) : "f"(f));
    return u;
}

__device__ __forceinline__ void mma_tf32(float* c, const uint32_t* a, const uint32_t* b) {
    asm volatile("mma.sync.aligned.m16n8k8.row.col.f32.tf32.tf32.f32 "
        "{%0,%1,%2,%3},{%4,%5,%6,%7},{%8,%9},{%0,%1,%2,%3};"
        : "+f"(c[0]), "+f"(c[1]), "+f"(c[2]), "+f"(c[3])
        : "r"(a[0]), "r"(a[1]), "r"(a[2]), "r"(a[3]), "r"(b[0]), "r"(b[1]));
}

// ---------------------------------------------------------------------------
// GroupNorm (unchanged: ~40us, bandwidth-trivial)
// ---------------------------------------------------------------------------
__global__ void groupnorm_kernel(const float* __restrict__ x,
                                 const float* __restrict__ w,
                                 const float* __restrict__ bias,
                                 float* __restrict__ xn)
{
    int bg = blockIdx.x;
    int bb = bg / NGROUPS, g = bg % NGROUPS;
    const float* xp = x  + ((size_t)bb*CH + g*CG) * HW_;
    float*       op = xn + ((size_t)bb*CH + g*CG) * HW_;
    const int NEL = CG * HW_;
    int tid = threadIdx.x;

    float s = 0.f, ss = 0.f;
    for (int i = tid*4; i < NEL; i += blockDim.x*4) {
        float4 v = *(const float4*)&xp[i];
        s  += v.x + v.y + v.z + v.w;
        ss += v.x*v.x + v.y*v.y + v.z*v.z + v.w*v.w;
    }
    __shared__ float r1[256], r2[256];
    r1[tid] = s; r2[tid] = ss;
    __syncthreads();
    for (int st = 128; st > 0; st >>= 1) {
        if (tid < st) { r1[tid] += r1[tid+st]; r2[tid] += r2[tid+st]; }
        __syncthreads();
    }
    float mean = r1[0] * (1.f/NEL);
    float var  = r2[0] * (1.f/NEL) - mean*mean;
    float inv  = rsqrtf(var + EPS_);

    for (int i = tid*4; i < NEL; i += blockDim.x*4) {
        int ch = g*CG + (i >> 10);
        float wc = w[ch], bc = bias[ch];
        float4 v = *(const float4*)&xp[i];
        float4 o;
        o.x = (v.x - mean)*inv*wc + bc;
        o.y = (v.y - mean)*inv*wc + bc;
        o.z = (v.z - mean)*inv*wc + bc;
        o.w = (v.w - mean)*inv*wc + bc;
        *(float4*)&op[i] = o;
    }
}

// ---------------------------------------------------------------------------
// tf32 MMA GEMM: C[bz] = A[MxK] * B[bz][KxN] + bias (+residual)
// 128x128x32 tile, 256 threads = 8 warps (2M x 4N), each warp 64x32.
// Smem: As[m][k] stride 36 (conflict-free A frags), Bs[k][n] stride 136.
// ---------------------------------------------------------------------------
#define GBM 128
#define GBN 128
#define GBK 32

__global__ __launch_bounds__(256)
void mma_gemm_kernel(const float* __restrict__ A,
                     const float* __restrict__ Bbase,
                     float* __restrict__ Cbase,
                     const float* __restrict__ bias,
                     const float* __restrict__ Rbase,
                     int M, int K, int N)
{
    __shared__ uint32_t As[GBM*36];
    __shared__ uint32_t Bs[GBK*136];

    int bz = blockIdx.z;
    const float* Bm = Bbase + (size_t)bz * K * N;
    float*       Cm = Cbase + (size_t)bz * M * N;
    const float* Rm = Rbase ? (Rbase + (size_t)bz * M * N) : (const float*)0;

    int m0 = blockIdx.y * GBM, n0 = blockIdx.x * GBN;
    int tid = threadIdx.x, lane = tid & 31, warp = tid >> 5;
    int wm = (warp >> 2) * 64, wn = (warp & 3) * 32;

    int arow = tid >> 3, acol = (tid & 7) * 4;   // A loader: rows arow+r*32, cols acol..+3
    int brow = tid >> 5, bcol = (tid & 31) * 4;  // B loader: rows brow+r*8, cols bcol..+3

    float c[4][4][4];
    #pragma unroll
    for (int mt = 0; mt < 4; mt++)
        #pragma unroll
        for (int nt = 0; nt < 4; nt++)
            #pragma unroll
            for (int e = 0; e < 4; e++) c[mt][nt][e] = 0.f;

    float4 areg[4], breg[4];
    #pragma unroll
    for (int r = 0; r < 4; r++) {
        areg[r] = *(const float4*)&A[(size_t)(m0 + arow + r*32)*K + acol];
        breg[r] = *(const float4*)&Bm[(size_t)(brow + r*8)*N + n0 + bcol];
    }

    for (int k0 = 0; k0 < K; k0 += GBK) {
        // store staged tile (convert to tf32)
        #pragma unroll
        for (int r = 0; r < 4; r++) {
            uint4 ua, ub;
            ua.x = f2tf32(areg[r].x); ua.y = f2tf32(areg[r].y);
            ua.z = f2tf32(areg[r].z); ua.w = f2tf32(areg[r].w);
            *(uint4*)&As[(arow + r*32)*36 + acol] = ua;
            ub.x = f2tf32(breg[r].x); ub.y = f2tf32(breg[r].y);
            ub.z = f2tf32(breg[r].z); ub.w = f2tf32(breg[r].w);
            *(uint4*)&Bs[(brow + r*8)*136 + bcol] = ub;
        }
        __syncthreads();

        if (k0 + GBK < K) {
            #pragma unroll
            for (int r = 0; r < 4; r++) {
                areg[r] = *(const float4*)&A[(size_t)(m0 + arow + r*32)*K + k0 + GBK + acol];
                breg[r] = *(const float4*)&Bm[(size_t)(brow + r*8)*N + k0 + GBK == 0 ? 0 : (size_t)(k0 + GBK + brow + r*8)*N + n0 + bcol];
            }
        }
        // NOTE: the B prefetch line above must index rows (k0+GBK+brow+r*8); rewrite cleanly:
        if (k0 + GBK < K) {
            #pragma unroll
            for (int r = 0; r < 4; r++) {
                areg[r] = *(const float4*)&A[(size_t)(m0 + arow + r*32)*K + (k0 + GBK) + acol];
                breg[r] = *(const float4*)&Bm[(size_t)((k0 + GBK) + brow + r*8)*N + n0 + bcol];
            }
        }

        #pragma unroll
        for (int ks = 0; ks < 4; ks++) {
            uint32_t a[4][4], b[4][2];
            #pragma unroll
            for (int mt = 0; mt < 4; mt++) {
                int row = wm + mt*16 + (lane >> 2);
                int col = ks*8 + (lane & 3);
                a[mt][0] = As[row*36 + col];
                a[mt][1] = As[(row+8)*36 + col];
                a[mt][2] = As[row*36 + col + 4];
                a[mt][3] = As[(row+8)*36 + col + 4];
            }
            #pragma unroll
            for (int nt = 0; nt < 4; nt++) {
                int kk = ks*8 + (lane & 3);
                int nn = wn + nt*8 + (lane >> 2);
                b[nt][0] = Bs[kk*136 + nn];
                b[nt][1] = Bs[(kk+4)*136 + nn];
            }
            #pragma unroll
            for (int mt = 0; mt < 4; mt++)
                #pragma unroll
                for (int nt = 0; nt < 4; nt++)
                    mma_tf32(c[mt][nt], a[mt], b[nt]);
        }
        __syncthreads();
    }

    // epilogue
    #pragma unroll
    for (int mt = 0; mt < 4; mt++) {
        #pragma unroll
        for (int half = 0; half < 2; half++) {
            int m = m0 + wm + mt*16 + (lane >> 2) + half*8;
            float bvv = bias ? bias[m] : 0.f;
            #pragma unroll
            for (int nt = 0; nt < 4; nt++) {
                int n = n0 + wn + nt*8 + 2*(lane & 3);
                float2 o;
                o.x = c[mt][nt][half*2 + 0] + bvv;
                o.y = c[mt][nt][half*2 + 1] + bvv;
                if (Rm) {
                    float2 r = *(const float2*)&Rm[(size_t)m*N + n];
                    o.x += r.x; o.y += r.y;
                }
                *(float2*)&Cm[(size_t)m*N + n] = o;
            }
        }
    }
}

// ---------------------------------------------------------------------------
// Flash attention with tf32 MMA. Block = 64 queries of one (b,h).
// 128 threads = 4 warps, warp owns 16 query rows. Q frags register-resident.
// Smem: Qs/Ps [64][68] (dual use), Ks [64][68], Vs [64][72]. 53248 B dynamic.
// ---------------------------------------------------------------------------
__global__ __launch_bounds__(128)
void attention_kernel(const float* __restrict__ qkv,
                      float* __restrict__ outp)
{
    extern __shared__ uint32_t smd[];
    uint32_t* Ps = smd;                 // [64][68] — Q staging, then P, then O out
    uint32_t* Ks = smd + 64*68;         // [64][68]  Ks[j][d]
    uint32_t* Vs = smd + 2*64*68;       // [64][72]  Vs[j][d]

    int bh = blockIdx.y;
    int bb = bh >> 3, hh = bh & 7;
    int i0 = blockIdx.x * 64;
    const float* qp = qkv + ((size_t)bb*3*CH + hh*HD) * HW_;
    const float* kp = qp + (size_t)CH * HW_;
    const float* vp = qp + (size_t)2*CH * HW_;

    int tid = threadIdx.x, lane = tid & 31, warp = tid >> 5;

    // stage Q (transpose to [i][d], tf32)
    #pragma unroll
    for (int e = 0; e < 32; e++) {
        int idx = e*128 + tid;
        int d = idx >> 6, i = idx & 63;
        Ps[i*68 + d] = f2tf32(qp[(size_t)d*HW_ + i0 + i]);
    }
    __syncthreads();

    // Q fragments, register resident: row block = warp*16
    uint32_t qf[8][4];
    {
        int row = warp*16 + (lane >> 2);
        #pragma unroll
        for (int ks = 0; ks < 8; ks++) {
            int col = ks*8 + (lane & 3);
            qf[ks][0] = Ps[row*68 + col];
            qf[ks][1] = Ps[(row+8)*68 + col];
            qf[ks][2] = Ps[row*68 + col + 4];
            qf[ks][3] = Ps[(row+8)*68 + col + 4];
        }
    }
    __syncthreads();

    float m0v = -1e30f, m1v = -1e30f, l0 = 0.f, l1 = 0.f;
    float o[8][4];
    #pragma unroll
    for (int dt = 0; dt < 8; dt++)
        #pragma unroll
        for (int e = 0; e < 4; e++) o[dt][e] = 0.f;

    for (int j0 = 0; j0 < HW_; j0 += 64) {
        __syncthreads();
        // load K, V tiles (transpose to [j][d], tf32)
        #pragma unroll
        for (int e = 0; e < 32; e++) {
            int idx = e*128 + tid;
            int d = idx >> 6, j = idx & 63;
            Ks[j*68 + d] = f2tf32(kp[(size_t)d*HW_ + j0 + j]);
            Vs[j*72 + d] = f2tf32(vp[(size_t)d*HW_ + j0 + j]);
        }
        __syncthreads();

        // S = Q K^T
        float s[8][4];
        #pragma unroll
        for (int nt = 0; nt < 8; nt++)
            #pragma unroll
            for (int e = 0; e < 4; e++) s[nt][e] = 0.f;

        #pragma unroll
        for (int ks = 0; ks < 8; ks++) {
            int kk = ks*8 + (lane & 3);
            #pragma unroll
            for (int nt = 0; nt < 8; nt++) {
                uint32_t b[2];
                int jj = nt*8 + (lane >> 2);
                b[0] = Ks[jj*68 + kk];
                b[1] = Ks[jj*68 + kk + 4];
                mma_tf32(s[nt], qf[ks], b);
            }
        }

        // online softmax: thread rows r0 = warp*16+lane/4, r1 = r0+8
        float rmax0 = -1e30f, rmax1 = -1e30f;
        #pragma unroll
        for (int nt = 0; nt < 8; nt++) {
            s[nt][0] *= SCALE_; s[nt][1] *= SCALE_;
            s[nt][2] *= SCALE_; s[nt][3] *= SCALE_;
            rmax0 = fmaxf(rmax0, fmaxf(s[nt][0], s[nt][1]));
            rmax1 = fmaxf(rmax1, fmaxf(s[nt][2], s[nt][3]));
        }
        #pragma unroll
        for (int off = 1; off < 4; off <<= 1) {
            rmax0 = fmaxf(rmax0, __shfl_xor_sync(0xffffffffu, rmax0, off));
            rmax1 = fmaxf(rmax1, __shfl_xor_sync(0xffffffffu, rmax1, off));
        }
        float mn0 = fmaxf(m0v, rmax0), mn1 = fmaxf(m1v, rmax1);
        float corr0 = __expf(m0v - mn0), corr1 = __expf(m1v - mn1);
        m0v = mn0; m1v = mn1;

        float rs0 = 0.f, rs1 = 0.f;
        #pragma unroll
        for (int nt = 0; nt < 8; nt++) {
            s[nt][0] = __expf(s[nt][0] - mn0);
            s[nt][1] = __expf(s[nt][1] - mn0);
            s[nt][2] = __expf(s[nt][2] - mn1);
            s[nt][3] = __expf(s[nt][3] - mn1);
            rs0 += s[nt][0] + s[nt][1];
            rs1 += s[nt][2] + s[nt][3];
        }
        #pragma unroll
        for (int off = 1; off < 4; off <<= 1) {
            rs0 += __shfl_xor_sync(0xffffffffu, rs0, off);
            rs1 += __shfl_xor_sync(0xffffffffu, rs1, off);
        }
        l0 = l0*corr0 + rs0;
        l1 = l1*corr1 + rs1;
        #pragma unroll
        for (int dt = 0; dt < 8; dt++) {
            o[dt][0] *= corr0; o[dt][1] *= corr0;
            o[dt][2] *= corr1; o[dt][3] *= corr1;
        }

        // write P (tf32) to smem for A-frag reload
        {
            int r0 = warp*16 + (lane >> 2);
            #pragma unroll
            for (int nt = 0; nt < 8; nt++) {
                int col = nt*8 + 2*(lane & 3);
                uint2 p0, p1;
                p0.x = f2tf32(s[nt][0]); p0.y = f2tf32(s[nt][1]);
                p1.x = f2tf32(s[nt][2]); p1.y = f2tf32(s[nt][3]);
                *(uint2*)&Ps[r0*68 + col]     = p0;
                *(uint2*)&Ps[(r0+8)*68 + col] = p1;
            }
        }
        __syncthreads();

        // O += P @ V
        #pragma unroll
        for (int ks = 0; ks < 8; ks++) {
            uint32_t pa[4];
            int row = warp*16 + (lane >> 2);
            int col = ks*8 + (lane & 3);
            pa[0] = Ps[row*68 + col];
            pa[1] = Ps[(row+8)*68 + col];
            pa[2] = Ps[row*68 + col + 4];
            pa[3] = Ps[(row+8)*68 + col + 4];
            int jj = ks*8 + (lane & 3);
            #pragma unroll
            for (int dt = 0; dt < 8; dt++) {
                uint32_t b[2];
                int dd = dt*8 + (lane >> 2);
                b[0] = Vs[jj*72 + dd];
                b[1] = Vs[(jj+4)*72 + dd];
                mma_tf32(o[dt], pa, b);
            }
        }
    }

    __syncthreads();
    // normalize, stage O (fp32) into Ps buffer as [i][d]
    {
        float* PsF = (float*)Ps;
        float inv0 = 1.f / l0, inv1 = 1.f / l1;
        int r0 = warp*16 + (lane >> 2);
        #pragma unroll
        for (int dt = 0; dt < 8; dt++) {
            int col = dt*8 + 2*(lane & 3);
            float2 v0, v1;
            v0.x = o[dt][0]*inv0; v0.y = o[dt][1]*inv0;
            v1.x = o[dt][2]*inv1; v1.y = o[dt][3]*inv1;
            *(float2*)&PsF[r0*68 + col]     = v0;
            *(float2*)&PsF[(r0+8)*68 + col] = v1;
        }
    }
    __syncthreads();

    // coalesced store out[d][i]
    float* ob = outp + ((size_t)bb*CH + hh*HD) * HW_;
    const float* PsF = (const float*)Ps;
    #pragma unroll
    for (int e = 0; e < 32; e++) {
        int idx = e*128 + tid;
        int d = idx >> 6, i = idx & 63;
        ob[(size_t)d*HW_ + i0 + i] = PsF[i*68 + d];
    }
}

// ---------------------------------------------------------------------------
extern "C" void kernel_launch(void* const* d_in, const int* in_sizes, int n_in,
                              void* d_out, int out_size)
{
    const float* x      = (const float*)d_in[0];
    const float* gn_w   = (const float*)d_in[1];
    const float* gn_b   = (const float*)d_in[2];
    const float* qkv_w  = (const float*)d_in[3];
    const float* qkv_b  = (const float*)d_in[4];
    const float* proj_w = (const float*)d_in[5];
    const float* proj_b = (const float*)d_in[6];
    float* out = (float*)d_out;

    float *xn, *qkvb, *att;
    cudaGetSymbolAddress((void**)&xn,   g_xn);
    cudaGetSymbolAddress((void**)&qkvb, g_qkv);
    cudaGetSymbolAddress((void**)&att,  g_att);

    const int ATT_SMEM = (64*68*2 + 64*72) * 4;  // 53248 B
    cudaFuncSetAttribute(attention_kernel,
                         cudaFuncAttributeMaxDynamicSharedMemorySize, ATT_SMEM);

    groupnorm_kernel<<<BATCH*NGROUPS, 256>>>(x, gn_w, gn_b, xn);

    mma_gemm_kernel<<<dim3(HW_/GBN, (3*CH)/GBM, BATCH), 256>>>(
        qkv_w, xn, qkvb, qkv_b, (const float*)0, 3*CH, CH, HW_);

    attention_kernel<<<dim3(HW_/64, BATCH*NH), 128, ATT_SMEM>>>(qkvb, att);

    mma_gemm_kernel<<<dim3(HW_/GBN, CH/GBM, BATCH), 256>>>(
        proj_w, att, out, proj_b, x, CH, CH, HW_);
}

// round 7
// speedup vs baseline: 2.1788x; 2.1788x over previous
#include <cuda_runtime.h>
#include <cuda_bf16.h>
#include <math.h>
#include <stdint.h>

#define BATCH   16
#define CH      512
#define HW_     1024
#define NGROUPS 8
#define CG      64
#define NH      8
#define HD      64
#define EPS_    1e-5f
#define SCALE_  0.125f

// Scratch (allocation-free) — all bf16 now
__device__ __nv_bfloat16 g_xn [BATCH*CH*HW_];
__device__ __nv_bfloat16 g_qkv[(size_t)BATCH*3*CH*HW_];
__device__ __nv_bfloat16 g_att[BATCH*CH*HW_];

// ---------------------------------------------------------------------------
// helpers
// ---------------------------------------------------------------------------
__device__ __forceinline__ uint32_t sptr(const void* p) {
    return (uint32_t)__cvta_generic_to_shared(p);
}
__device__ __forceinline__ uint32_t packbf(float a, float b) {
    __nv_bfloat162 t = __float22bfloat162_rn(make_float2(a, b));
    return *(uint32_t*)&t;
}
__device__ __forceinline__ void ldsm4(uint32_t* r, uint32_t a) {
    asm volatile("ldmatrix.sync.aligned.m8n8.x4.shared.b16 {%0,%1,%2,%3},[%4];"
        : "=r"(r[0]), "=r"(r[1]), "=r"(r[2]), "=r"(r[3]) : "r"(a));
}
__device__ __forceinline__ void ldsm4t(uint32_t* r, uint32_t a) {
    asm volatile("ldmatrix.sync.aligned.m8n8.x4.trans.shared.b16 {%0,%1,%2,%3},[%4];"
        : "=r"(r[0]), "=r"(r[1]), "=r"(r[2]), "=r"(r[3]) : "r"(a));
}
__device__ __forceinline__ void ldsm2(uint32_t* r, uint32_t a) {
    asm volatile("ldmatrix.sync.aligned.m8n8.x2.shared.b16 {%0,%1},[%2];"
        : "=r"(r[0]), "=r"(r[1]) : "r"(a));
}
__device__ __forceinline__ void ldsm2t(uint32_t* r, uint32_t a) {
    asm volatile("ldmatrix.sync.aligned.m8n8.x2.trans.shared.b16 {%0,%1},[%2];"
        : "=r"(r[0]), "=r"(r[1]) : "r"(a));
}
__device__ __forceinline__ void mma_bf16(float* c, const uint32_t* a, const uint32_t* b) {
    asm volatile("mma.sync.aligned.m16n8k16.row.col.f32.bf16.bf16.f32 "
        "{%0,%1,%2,%3},{%4,%5,%6,%7},{%8,%9},{%0,%1,%2,%3};"
        : "+f"(c[0]), "+f"(c[1]), "+f"(c[2]), "+f"(c[3])
        : "r"(a[0]), "r"(a[1]), "r"(a[2]), "r"(a[3]), "r"(b[0]), "r"(b[1]));
}

// ---------------------------------------------------------------------------
// GroupNorm -> bf16 output
// ---------------------------------------------------------------------------
__global__ void groupnorm_kernel(const float* __restrict__ x,
                                 const float* __restrict__ w,
                                 const float* __restrict__ bias,
                                 __nv_bfloat16* __restrict__ xn)
{
    int bg = blockIdx.x;
    int bb = bg / NGROUPS, g = bg % NGROUPS;
    const float*   xp = x  + ((size_t)bb*CH + g*CG) * HW_;
    __nv_bfloat16* op = xn + ((size_t)bb*CH + g*CG) * HW_;
    const int NEL = CG * HW_;
    int tid = threadIdx.x;

    float s = 0.f, ss = 0.f;
    for (int i = tid*4; i < NEL; i += blockDim.x*4) {
        float4 v = *(const float4*)&xp[i];
        s  += v.x + v.y + v.z + v.w;
        ss += v.x*v.x + v.y*v.y + v.z*v.z + v.w*v.w;
    }
    __shared__ float r1[256], r2[256];
    r1[tid] = s; r2[tid] = ss;
    __syncthreads();
    for (int st = 128; st > 0; st >>= 1) {
        if (tid < st) { r1[tid] += r1[tid+st]; r2[tid] += r2[tid+st]; }
        __syncthreads();
    }
    float mean = r1[0] * (1.f/NEL);
    float var  = r2[0] * (1.f/NEL) - mean*mean;
    float inv  = rsqrtf(var + EPS_);

    for (int i = tid*4; i < NEL; i += blockDim.x*4) {
        int ch = g*CG + (i >> 10);
        float wc = w[ch], bc = bias[ch];
        float4 v = *(const float4*)&xp[i];
        uint2 o;
        o.x = packbf((v.x - mean)*inv*wc + bc, (v.y - mean)*inv*wc + bc);
        o.y = packbf((v.z - mean)*inv*wc + bc, (v.w - mean)*inv*wc + bc);
        *(uint2*)&op[i] = o;
    }
}

// ---------------------------------------------------------------------------
// bf16 MMA GEMM: C[bz] = A[MxK](fp32) * B[bz][KxN](bf16) + bias
// 128x128x32, 256 thr = 8 warps (2x4), warp 64x32, m16n8k16, double-buffered.
// As[m][k] stride 40 halves; Bs[k][n] stride 136 halves. ldmatrix frag loads.
// OUT_BF16: bf16 out, rows m<q_rows scaled by SCALE_.  else: fp32 + residual.
// ---------------------------------------------------------------------------
#define GBM 128
#define GBN 128
#define GBK 32
#define ASTR 40
#define BSTR 136

template<bool OUT_BF16>
__global__ __launch_bounds__(256)
void mma_gemm_kernel(const float* __restrict__ A,
                     const __nv_bfloat16* __restrict__ Bbase,
                     void* __restrict__ Cbase,
                     const float* __restrict__ bias,
                     const float* __restrict__ Rbase,
                     int M, int K, int N, int q_rows)
{
    __shared__ __align__(16) uint16_t As[2][GBM*ASTR];
    __shared__ __align__(16) uint16_t Bs[2][GBK*BSTR];

    int bz = blockIdx.z;
    const __nv_bfloat16* Bm = Bbase + (size_t)bz * K * N;

    int m0 = blockIdx.y * GBM, n0 = blockIdx.x * GBN;
    int tid = threadIdx.x, lane = tid & 31, warp = tid >> 5;
    int wm = (warp >> 2) * 64, wn = (warp & 3) * 32;

    int arow = tid >> 1, acol = (tid & 1) * 16;   // 16 consecutive k per thread
    int brow = tid >> 3, bcol = (tid & 7) * 16;   // 16 consecutive n per thread

    float c[4][4][4];
    #pragma unroll
    for (int mt = 0; mt < 4; mt++)
        #pragma unroll
        for (int nt = 0; nt < 4; nt++)
            #pragma unroll
            for (int e = 0; e < 4; e++) c[mt][nt][e] = 0.f;

    float4 af[4];
    uint4  bfv[2];

    // prefetch tile 0
    #pragma unroll
    for (int j = 0; j < 4; j++)
        af[j] = *(const float4*)&A[(size_t)(m0 + arow)*K + acol + j*4];
    bfv[0] = *(const uint4*)&Bm[(size_t)brow*N + n0 + bcol];
    bfv[1] = *(const uint4*)&Bm[(size_t)brow*N + n0 + bcol + 8];

    // store tile 0 -> buf 0
    {
        uint32_t p[8];
        #pragma unroll
        for (int j = 0; j < 4; j++) {
            p[2*j]   = packbf(af[j].x, af[j].y);
            p[2*j+1] = packbf(af[j].z, af[j].w);
        }
        *(uint4*)&As[0][arow*ASTR + acol]     = make_uint4(p[0], p[1], p[2], p[3]);
        *(uint4*)&As[0][arow*ASTR + acol + 8] = make_uint4(p[4], p[5], p[6], p[7]);
        *(uint4*)&Bs[0][brow*BSTR + bcol]     = bfv[0];
        *(uint4*)&Bs[0][brow*BSTR + bcol + 8] = bfv[1];
    }
    __syncthreads();

    const int KT = K / GBK;
    for (int kt = 0; kt < KT; kt++) {
        int buf = kt & 1;
        if (kt + 1 < KT) {
            int k0 = (kt + 1) * GBK;
            #pragma unroll
            for (int j = 0; j < 4; j++)
                af[j] = *(const float4*)&A[(size_t)(m0 + arow)*K + k0 + acol + j*4];
            bfv[0] = *(const uint4*)&Bm[(size_t)(k0 + brow)*N + n0 + bcol];
            bfv[1] = *(const uint4*)&Bm[(size_t)(k0 + brow)*N + n0 + bcol + 8];
        }

        #pragma unroll
        for (int ks = 0; ks < 2; ks++) {
            uint32_t a[4][4], b[4][2];
            int g = lane >> 3;
            #pragma unroll
            for (int mt = 0; mt < 4; mt++) {
                int row = wm + mt*16 + (g & 1)*8 + (lane & 7);
                int col = ks*16 + (g >> 1)*8;
                ldsm4(a[mt], sptr(&As[buf][row*ASTR + col]));
            }
            int kk = ks*16 + (lane & 15);
            #pragma unroll
            for (int nt = 0; nt < 4; nt++)
                ldsm2t(b[nt], sptr(&Bs[buf][kk*BSTR + wn + nt*8]));
            #pragma unroll
            for (int mt = 0; mt < 4; mt++)
                #pragma unroll
                for (int nt = 0; nt < 4; nt++)
                    mma_bf16(c[mt][nt], a[mt], b[nt]);
        }

        if (kt + 1 < KT) {
            int nb = (kt + 1) & 1;
            uint32_t p[8];
            #pragma unroll
            for (int j = 0; j < 4; j++) {
                p[2*j]   = packbf(af[j].x, af[j].y);
                p[2*j+1] = packbf(af[j].z, af[j].w);
            }
            *(uint4*)&As[nb][arow*ASTR + acol]     = make_uint4(p[0], p[1], p[2], p[3]);
            *(uint4*)&As[nb][arow*ASTR + acol + 8] = make_uint4(p[4], p[5], p[6], p[7]);
            *(uint4*)&Bs[nb][brow*BSTR + bcol]     = bfv[0];
            *(uint4*)&Bs[nb][brow*BSTR + bcol + 8] = bfv[1];
            __syncthreads();
        }
    }

    // epilogue
    #pragma unroll
    for (int mt = 0; mt < 4; mt++) {
        #pragma unroll
        for (int half = 0; half < 2; half++) {
            int m = m0 + wm + mt*16 + (lane >> 2) + half*8;
            float bv = bias ? bias[m] : 0.f;
            #pragma unroll
            for (int nt = 0; nt < 4; nt++) {
                int n = n0 + wn + nt*8 + 2*(lane & 3);
                float x0 = c[mt][nt][half*2 + 0] + bv;
                float x1 = c[mt][nt][half*2 + 1] + bv;
                if (OUT_BF16) {
                    float sc = (m < q_rows) ? SCALE_ : 1.0f;
                    uint32_t pw = packbf(x0*sc, x1*sc);
                    *(uint32_t*)((__nv_bfloat16*)Cbase + (size_t)bz*M*N + (size_t)m*N + n) = pw;
                } else {
                    float2 o = make_float2(x0, x1);
                    if (Rbase) {
                        float2 r = *(const float2*)&Rbase[(size_t)bz*M*N + (size_t)m*N + n];
                        o.x += r.x; o.y += r.y;
                    }
                    *(float2*)((float*)Cbase + (size_t)bz*M*N + (size_t)m*N + n) = o;
                }
            }
        }
    }
}

// ---------------------------------------------------------------------------
// Flash attention, bf16 MMA. Block = 64 queries of one (b,h), 4 warps.
// All tiles kept in natural [d][token] layout; ldmatrix(.trans) does the
// transposes. Q pre-scaled by 1/8 in the qkv epilogue.
// ---------------------------------------------------------------------------
#define QSTR 72   // smem row stride in halves (64 + 8 pad) -> conflict-free

__global__ __launch_bounds__(128)
void attention_kernel(const __nv_bfloat16* __restrict__ qkv,
                      __nv_bfloat16* __restrict__ outp)
{
    __shared__ __align__(16) uint16_t Qs[64*QSTR];  // [d][i]
    __shared__ __align__(16) uint16_t Ks[64*QSTR];  // [d][j]
    __shared__ __align__(16) uint16_t Vs[64*QSTR];  // [d][j]
    __shared__ __align__(16) uint16_t Ps[64*QSTR];  // [i][j]; reused as O [d][i]

    int bh = blockIdx.y;
    int bb = bh >> 3, hh = bh & 7;
    int i0 = blockIdx.x * 64;
    const __nv_bfloat16* qp = qkv + ((size_t)bb*3*CH + hh*HD) * HW_;
    const __nv_bfloat16* kp = qp + (size_t)CH * HW_;
    const __nv_bfloat16* vp = qp + (size_t)2*CH * HW_;

    int tid = threadIdx.x, lane = tid & 31, warp = tid >> 5;

    // copy Q tile (natural layout, 16B vectors)
    #pragma unroll
    for (int r = 0; r < 4; r++) {
        int idx = r*128 + tid;
        int d = idx >> 3, cc = (idx & 7) * 8;
        *(uint4*)&Qs[d*QSTR + cc] = *(const uint4*)&qp[(size_t)d*HW_ + i0 + cc];
    }
    __syncthreads();

    // Q fragments register-resident (A col-major via ldmatrix.x4.trans)
    uint32_t qf[4][4];
    {
        int g = lane >> 3;
        int mq = warp*16 + (g & 1)*8;
        int kq = (g >> 1)*8 + (lane & 7);
        #pragma unroll
        for (int ks = 0; ks < 4; ks++)
            ldsm4t(qf[ks], sptr(&Qs[(ks*16 + kq)*QSTR + mq]));
    }

    float mx0 = -1e30f, mx1 = -1e30f, l0 = 0.f, l1 = 0.f;
    float o[8][4];
    #pragma unroll
    for (int nt = 0; nt < 8; nt++)
        #pragma unroll
        for (int e = 0; e < 4; e++) o[nt][e] = 0.f;

    for (int j0 = 0; j0 < HW_; j0 += 64) {
        __syncthreads();
        #pragma unroll
        for (int r = 0; r < 4; r++) {
            int idx = r*128 + tid;
            int d = idx >> 3, cc = (idx & 7) * 8;
            *(uint4*)&Ks[d*QSTR + cc] = *(const uint4*)&kp[(size_t)d*HW_ + j0 + cc];
            *(uint4*)&Vs[d*QSTR + cc] = *(const uint4*)&vp[(size_t)d*HW_ + j0 + cc];
        }
        __syncthreads();

        // S = Q K^T (q pre-scaled)
        float s[8][4];
        #pragma unroll
        for (int nt = 0; nt < 8; nt++)
            #pragma unroll
            for (int e = 0; e < 4; e++) s[nt][e] = 0.f;

        #pragma unroll
        for (int ks = 0; ks < 4; ks++) {
            int kk = ks*16 + (lane & 15);
            #pragma unroll
            for (int nt = 0; nt < 8; nt++) {
                uint32_t b[2];
                ldsm2t(b, sptr(&Ks[kk*QSTR + nt*8]));
                mma_bf16(s[nt], qf[ks], b);
            }
        }

        // online softmax (rows r0 = warp*16 + lane/4, r1 = r0+8)
        float rmax0 = -1e30f, rmax1 = -1e30f;
        #pragma unroll
        for (int nt = 0; nt < 8; nt++) {
            rmax0 = fmaxf(rmax0, fmaxf(s[nt][0], s[nt][1]));
            rmax1 = fmaxf(rmax1, fmaxf(s[nt][2], s[nt][3]));
        }
        #pragma unroll
        for (int off = 1; off < 4; off <<= 1) {
            rmax0 = fmaxf(rmax0, __shfl_xor_sync(0xffffffffu, rmax0, off));
            rmax1 = fmaxf(rmax1, __shfl_xor_sync(0xffffffffu, rmax1, off));
        }
        float mn0 = fmaxf(mx0, rmax0), mn1 = fmaxf(mx1, rmax1);
        float corr0 = __expf(mx0 - mn0), corr1 = __expf(mx1 - mn1);
        mx0 = mn0; mx1 = mn1;

        float rs0 = 0.f, rs1 = 0.f;
        #pragma unroll
        for (int nt = 0; nt < 8; nt++) {
            s[nt][0] = __expf(s[nt][0] - mn0);
            s[nt][1] = __expf(s[nt][1] - mn0);
            s[nt][2] = __expf(s[nt][2] - mn1);
            s[nt][3] = __expf(s[nt][3] - mn1);
            rs0 += s[nt][0] + s[nt][1];
            rs1 += s[nt][2] + s[nt][3];
        }
        #pragma unroll
        for (int off = 1; off < 4; off <<= 1) {
            rs0 += __shfl_xor_sync(0xffffffffu, rs0, off);
            rs1 += __shfl_xor_sync(0xffffffffu, rs1, off);
        }
        l0 = l0*corr0 + rs0;
        l1 = l1*corr1 + rs1;
        #pragma unroll
        for (int nt = 0; nt < 8; nt++) {
            o[nt][0] *= corr0; o[nt][1] *= corr0;
            o[nt][2] *= corr1; o[nt][3] *= corr1;
        }

        // write P (bf16) — warp-private rows, warp sync only
        {
            int r0 = warp*16 + (lane >> 2);
            #pragma unroll
            for (int nt = 0; nt < 8; nt++) {
                int colj = nt*8 + 2*(lane & 3);
                *(uint32_t*)&Ps[r0*QSTR + colj]     = packbf(s[nt][0], s[nt][1]);
                *(uint32_t*)&Ps[(r0+8)*QSTR + colj] = packbf(s[nt][2], s[nt][3]);
            }
        }
        __syncwarp();

        // O += P @ V
        #pragma unroll
        for (int ks = 0; ks < 4; ks++) {
            uint32_t pa[4];
            {
                int g = lane >> 3;
                int row = warp*16 + (g & 1)*8 + (lane & 7);
                int col = ks*16 + (g >> 1)*8;
                ldsm4(pa, sptr(&Ps[row*QSTR + col]));
            }
            int jc = ks*16 + ((lane & 15) >> 3)*8;
            #pragma unroll
            for (int nt = 0; nt < 8; nt++) {
                uint32_t b[2];
                int dr = nt*8 + (lane & 7);
                ldsm2(b, sptr(&Vs[dr*QSTR + jc]));
                mma_bf16(o[nt], pa, b);
            }
        }
    }

    __syncthreads();   // everyone done with Ps before reuse as O stage
    // normalize + stage O as bf16 [d][i] into Ps
    {
        float inv0 = 1.f / l0, inv1 = 1.f / l1;
        int iq = warp*16 + (lane >> 2);
        __nv_bfloat16* Od = (__nv_bfloat16*)Ps;
        #pragma unroll
        for (int nt = 0; nt < 8; nt++) {
            int d = nt*8 + 2*(lane & 3);
            Od[(size_t)d*QSTR + iq]         = __float2bfloat16_rn(o[nt][0]*inv0);
            Od[(size_t)(d+1)*QSTR + iq]     = __float2bfloat16_rn(o[nt][1]*inv0);
            Od[(size_t)d*QSTR + iq + 8]     = __float2bfloat16_rn(o[nt][2]*inv1);
            Od[(size_t)(d+1)*QSTR + iq + 8] = __float2bfloat16_rn(o[nt][3]*inv1);
        }
    }
    __syncthreads();

    // coalesced store out[d][i]
    __nv_bfloat16* ob = outp + ((size_t)bb*CH + hh*HD) * HW_;
    #pragma unroll
    for (int r = 0; r < 4; r++) {
        int idx = r*128 + tid;
        int d = idx >> 3, cc = (idx & 7) * 8;
        *(uint4*)&ob[(size_t)d*HW_ + i0 + cc] = *(const uint4*)&Ps[d*QSTR + cc];
    }
}

// ---------------------------------------------------------------------------
extern "C" void kernel_launch(void* const* d_in, const int* in_sizes, int n_in,
                              void* d_out, int out_size)
{
    const float* x      = (const float*)d_in[0];
    const float* gn_w   = (const float*)d_in[1];
    const float* gn_b   = (const float*)d_in[2];
    const float* qkv_w  = (const float*)d_in[3];
    const float* qkv_b  = (const float*)d_in[4];
    const float* proj_w = (const float*)d_in[5];
    const float* proj_b = (const float*)d_in[6];
    float* out = (float*)d_out;

    __nv_bfloat16 *xn, *qkvb, *att;
    cudaGetSymbolAddress((void**)&xn,   g_xn);
    cudaGetSymbolAddress((void**)&qkvb, g_qkv);
    cudaGetSymbolAddress((void**)&att,  g_att);

    // 1) GroupNorm -> bf16
    groupnorm_kernel<<<BATCH*NGROUPS, 256>>>(x, gn_w, gn_b, xn);

    // 2) qkv GEMM (bf16 out, q rows pre-scaled by 1/8)
    mma_gemm_kernel<true><<<dim3(HW_/GBN, (3*CH)/GBM, BATCH), 256>>>(
        qkv_w, xn, qkvb, qkv_b, (const float*)0, 3*CH, CH, HW_, CH);

    // 3) fused flash attention (bf16 in/out)
    attention_kernel<<<dim3(HW_/64, BATCH*NH), 128>>>(qkvb, att);

    // 4) proj GEMM (fp32 out + bias + residual)
    mma_gemm_kernel<false><<<dim3(HW_/GBN, CH/GBM, BATCH), 256>>>(
        proj_w, att, out, proj_b, x, CH, CH, HW_, 0);
}

// round 8
// speedup vs baseline: 2.1877x; 1.0041x over previous
#include <cuda_runtime.h>
#include <cuda_bf16.h>
#include <math.h>
#include <stdint.h>

#define BATCH   16
#define CH      512
#define HW_     1024
#define NGROUPS 8
#define CG      64
#define NH      8
#define HD      64
#define EPS_    1e-5f
#define SCALE_  0.125f

// Scratch (allocation-free) — all bf16 now
__device__ __nv_bfloat16 g_xn [BATCH*CH*HW_];
__device__ __nv_bfloat16 g_qkv[(size_t)BATCH*3*CH*HW_];
__device__ __nv_bfloat16 g_att[BATCH*CH*HW_];

// ---------------------------------------------------------------------------
// helpers
// ---------------------------------------------------------------------------
__device__ __forceinline__ uint32_t sptr(const void* p) {
    return (uint32_t)__cvta_generic_to_shared(p);
}
__device__ __forceinline__ uint32_t packbf(float a, float b) {
    __nv_bfloat162 t = __float22bfloat162_rn(make_float2(a, b));
    return *(uint32_t*)&t;
}
__device__ __forceinline__ void ldsm4(uint32_t* r, uint32_t a) {
    asm volatile("ldmatrix.sync.aligned.m8n8.x4.shared.b16 {%0,%1,%2,%3},[%4];"
        : "=r"(r[0]), "=r"(r[1]), "=r"(r[2]), "=r"(r[3]) : "r"(a));
}
__device__ __forceinline__ void ldsm4t(uint32_t* r, uint32_t a) {
    asm volatile("ldmatrix.sync.aligned.m8n8.x4.trans.shared.b16 {%0,%1,%2,%3},[%4];"
        : "=r"(r[0]), "=r"(r[1]), "=r"(r[2]), "=r"(r[3]) : "r"(a));
}
__device__ __forceinline__ void ldsm2(uint32_t* r, uint32_t a) {
    asm volatile("ldmatrix.sync.aligned.m8n8.x2.shared.b16 {%0,%1},[%2];"
        : "=r"(r[0]), "=r"(r[1]) : "r"(a));
}
__device__ __forceinline__ void ldsm2t(uint32_t* r, uint32_t a) {
    asm volatile("ldmatrix.sync.aligned.m8n8.x2.trans.shared.b16 {%0,%1},[%2];"
        : "=r"(r[0]), "=r"(r[1]) : "r"(a));
}
__device__ __forceinline__ void mma_bf16(float* c, const uint32_t* a, const uint32_t* b) {
    asm volatile("mma.sync.aligned.m16n8k16.row.col.f32.bf16.bf16.f32 "
        "{%0,%1,%2,%3},{%4,%5,%6,%7},{%8,%9},{%0,%1,%2,%3};"
        : "+f"(c[0]), "+f"(c[1]), "+f"(c[2]), "+f"(c[3])
        : "r"(a[0]), "r"(a[1]), "r"(a[2]), "r"(a[3]), "r"(b[0]), "r"(b[1]));
}

// ---------------------------------------------------------------------------
// GroupNorm -> bf16 output
// ---------------------------------------------------------------------------
__global__ void groupnorm_kernel(const float* __restrict__ x,
                                 const float* __restrict__ w,
                                 const float* __restrict__ bias,
                                 __nv_bfloat16* __restrict__ xn)
{
    int bg = blockIdx.x;
    int bb = bg / NGROUPS, g = bg % NGROUPS;
    const float*   xp = x  + ((size_t)bb*CH + g*CG) * HW_;
    __nv_bfloat16* op = xn + ((size_t)bb*CH + g*CG) * HW_;
    const int NEL = CG * HW_;
    int tid = threadIdx.x;

    float s = 0.f, ss = 0.f;
    for (int i = tid*4; i < NEL; i += blockDim.x*4) {
        float4 v = *(const float4*)&xp[i];
        s  += v.x + v.y + v.z + v.w;
        ss += v.x*v.x + v.y*v.y + v.z*v.z + v.w*v.w;
    }
    __shared__ float r1[256], r2[256];
    r1[tid] = s; r2[tid] = ss;
    __syncthreads();
    for (int st = 128; st > 0; st >>= 1) {
        if (tid < st) { r1[tid] += r1[tid+st]; r2[tid] += r2[tid+st]; }
        __syncthreads();
    }
    float mean = r1[0] * (1.f/NEL);
    float var  = r2[0] * (1.f/NEL) - mean*mean;
    float inv  = rsqrtf(var + EPS_);

    for (int i = tid*4; i < NEL; i += blockDim.x*4) {
        int ch = g*CG + (i >> 10);
        float wc = w[ch], bc = bias[ch];
        float4 v = *(const float4*)&xp[i];
        uint2 o;
        o.x = packbf((v.x - mean)*inv*wc + bc, (v.y - mean)*inv*wc + bc);
        o.y = packbf((v.z - mean)*inv*wc + bc, (v.w - mean)*inv*wc + bc);
        *(uint2*)&op[i] = o;
    }
}

// ---------------------------------------------------------------------------
// bf16 MMA GEMM: C[bz] = A[MxK](fp32) * B[bz][KxN](bf16) + bias
// 128x128x32, 256 thr = 8 warps (2x4), warp 64x32, m16n8k16, double-buffered.
// As[m][k] stride 40 halves; Bs[k][n] stride 136 halves. ldmatrix frag loads.
// OUT_BF16: bf16 out, rows m<q_rows scaled by SCALE_.  else: fp32 + residual.
// ---------------------------------------------------------------------------
#define GBM 128
#define GBN 128
#define GBK 32
#define ASTR 40
#define BSTR 136

template<bool OUT_BF16>
__global__ __launch_bounds__(256)
void mma_gemm_kernel(const float* __restrict__ A,
                     const __nv_bfloat16* __restrict__ Bbase,
                     void* __restrict__ Cbase,
                     const float* __restrict__ bias,
                     const float* __restrict__ Rbase,
                     int M, int K, int N, int q_rows)
{
    __shared__ __align__(16) uint16_t As[2][GBM*ASTR];
    __shared__ __align__(16) uint16_t Bs[2][GBK*BSTR];

    int bz = blockIdx.z;
    const __nv_bfloat16* Bm = Bbase + (size_t)bz * K * N;

    int m0 = blockIdx.y * GBM, n0 = blockIdx.x * GBN;
    int tid = threadIdx.x, lane = tid & 31, warp = tid >> 5;
    int wm = (warp >> 2) * 64, wn = (warp & 3) * 32;

    int arow = tid >> 1, acol = (tid & 1) * 16;   // 16 consecutive k per thread
    int brow = tid >> 3, bcol = (tid & 7) * 16;   // 16 consecutive n per thread

    float c[4][4][4];
    #pragma unroll
    for (int mt = 0; mt < 4; mt++)
        #pragma unroll
        for (int nt = 0; nt < 4; nt++)
            #pragma unroll
            for (int e = 0; e < 4; e++) c[mt][nt][e] = 0.f;

    float4 af[4];
    uint4  bfv[2];

    // prefetch tile 0
    #pragma unroll
    for (int j = 0; j < 4; j++)
        af[j] = *(const float4*)&A[(size_t)(m0 + arow)*K + acol + j*4];
    bfv[0] = *(const uint4*)&Bm[(size_t)brow*N + n0 + bcol];
    bfv[1] = *(const uint4*)&Bm[(size_t)brow*N + n0 + bcol + 8];

    // store tile 0 -> buf 0
    {
        uint32_t p[8];
        #pragma unroll
        for (int j = 0; j < 4; j++) {
            p[2*j]   = packbf(af[j].x, af[j].y);
            p[2*j+1] = packbf(af[j].z, af[j].w);
        }
        *(uint4*)&As[0][arow*ASTR + acol]     = make_uint4(p[0], p[1], p[2], p[3]);
        *(uint4*)&As[0][arow*ASTR + acol + 8] = make_uint4(p[4], p[5], p[6], p[7]);
        *(uint4*)&Bs[0][brow*BSTR + bcol]     = bfv[0];
        *(uint4*)&Bs[0][brow*BSTR + bcol + 8] = bfv[1];
    }
    __syncthreads();

    const int KT = K / GBK;
    for (int kt = 0; kt < KT; kt++) {
        int buf = kt & 1;
        if (kt + 1 < KT) {
            int k0 = (kt + 1) * GBK;
            #pragma unroll
            for (int j = 0; j < 4; j++)
                af[j] = *(const float4*)&A[(size_t)(m0 + arow)*K + k0 + acol + j*4];
            bfv[0] = *(const uint4*)&Bm[(size_t)(k0 + brow)*N + n0 + bcol];
            bfv[1] = *(const uint4*)&Bm[(size_t)(k0 + brow)*N + n0 + bcol + 8];
        }

        #pragma unroll
        for (int ks = 0; ks < 2; ks++) {
            uint32_t a[4][4], b[4][2];
            int g = lane >> 3;
            #pragma unroll
            for (int mt = 0; mt < 4; mt++) {
                int row = wm + mt*16 + (g & 1)*8 + (lane & 7);
                int col = ks*16 + (g >> 1)*8;
                ldsm4(a[mt], sptr(&As[buf][row*ASTR + col]));
            }
            int kk = ks*16 + (lane & 15);
            #pragma unroll
            for (int nt = 0; nt < 4; nt++)
                ldsm2t(b[nt], sptr(&Bs[buf][kk*BSTR + wn + nt*8]));
            #pragma unroll
            for (int mt = 0; mt < 4; mt++)
                #pragma unroll
                for (int nt = 0; nt < 4; nt++)
                    mma_bf16(c[mt][nt], a[mt], b[nt]);
        }

        if (kt + 1 < KT) {
            int nb = (kt + 1) & 1;
            uint32_t p[8];
            #pragma unroll
            for (int j = 0; j < 4; j++) {
                p[2*j]   = packbf(af[j].x, af[j].y);
                p[2*j+1] = packbf(af[j].z, af[j].w);
            }
            *(uint4*)&As[nb][arow*ASTR + acol]     = make_uint4(p[0], p[1], p[2], p[3]);
            *(uint4*)&As[nb][arow*ASTR + acol + 8] = make_uint4(p[4], p[5], p[6], p[7]);
            *(uint4*)&Bs[nb][brow*BSTR + bcol]     = bfv[0];
            *(uint4*)&Bs[nb][brow*BSTR + bcol + 8] = bfv[1];
            __syncthreads();
        }
    }

    // epilogue
    #pragma unroll
    for (int mt = 0; mt < 4; mt++) {
        #pragma unroll
        for (int half = 0; half < 2; half++) {
            int m = m0 + wm + mt*16 + (lane >> 2) + half*8;
            float bv = bias ? bias[m] : 0.f;
            #pragma unroll
            for (int nt = 0; nt < 4; nt++) {
                int n = n0 + wn + nt*8 + 2*(lane & 3);
                float x0 = c[mt][nt][half*2 + 0] + bv;
                float x1 = c[mt][nt][half*2 + 1] + bv;
                if (OUT_BF16) {
                    float sc = (m < q_rows) ? SCALE_ : 1.0f;
                    uint32_t pw = packbf(x0*sc, x1*sc);
                    *(uint32_t*)((__nv_bfloat16*)Cbase + (size_t)bz*M*N + (size_t)m*N + n) = pw;
                } else {
                    float2 o = make_float2(x0, x1);
                    if (Rbase) {
                        float2 r = *(const float2*)&Rbase[(size_t)bz*M*N + (size_t)m*N + n];
                        o.x += r.x; o.y += r.y;
                    }
                    *(float2*)((float*)Cbase + (size_t)bz*M*N + (size_t)m*N + n) = o;
                }
            }
        }
    }
}

// ---------------------------------------------------------------------------
// Flash attention, bf16 MMA. Block = 64 queries of one (b,h), 4 warps.
// All tiles kept in natural [d][token] layout; ldmatrix(.trans) does the
// transposes. Q pre-scaled by 1/8 in the qkv epilogue.
// ---------------------------------------------------------------------------
#define QSTR 72   // smem row stride in halves (64 + 8 pad) -> conflict-free

__global__ __launch_bounds__(128)
void attention_kernel(const __nv_bfloat16* __restrict__ qkv,
                      __nv_bfloat16* __restrict__ outp)
{
    __shared__ __align__(16) uint16_t Qs[64*QSTR];  // [d][i]
    __shared__ __align__(16) uint16_t Ks[64*QSTR];  // [d][j]
    __shared__ __align__(16) uint16_t Vs[64*QSTR];  // [d][j]
    __shared__ __align__(16) uint16_t Ps[64*QSTR];  // [i][j]; reused as O [d][i]

    int bh = blockIdx.y;
    int bb = bh >> 3, hh = bh & 7;
    int i0 = blockIdx.x * 64;
    const __nv_bfloat16* qp = qkv + ((size_t)bb*3*CH + hh*HD) * HW_;
    const __nv_bfloat16* kp = qp + (size_t)CH * HW_;
    const __nv_bfloat16* vp = qp + (size_t)2*CH * HW_;

    int tid = threadIdx.x, lane = tid & 31, warp = tid >> 5;

    // copy Q tile (natural layout, 16B vectors)
    #pragma unroll
    for (int r = 0; r < 4; r++) {
        int idx = r*128 + tid;
        int d = idx >> 3, cc = (idx & 7) * 8;
        *(uint4*)&Qs[d*QSTR + cc] = *(const uint4*)&qp[(size_t)d*HW_ + i0 + cc];
    }
    __syncthreads();

    // Q fragments register-resident (A col-major via ldmatrix.x4.trans)
    uint32_t qf[4][4];
    {
        int g = lane >> 3;
        int mq = warp*16 + (g & 1)*8;
        int kq = (g >> 1)*8 + (lane & 7);
        #pragma unroll
        for (int ks = 0; ks < 4; ks++)
            ldsm4t(qf[ks], sptr(&Qs[(ks*16 + kq)*QSTR + mq]));
    }

    float mx0 = -1e30f, mx1 = -1e30f, l0 = 0.f, l1 = 0.f;
    float o[8][4];
    #pragma unroll
    for (int nt = 0; nt < 8; nt++)
        #pragma unroll
        for (int e = 0; e < 4; e++) o[nt][e] = 0.f;

    for (int j0 = 0; j0 < HW_; j0 += 64) {
        __syncthreads();
        #pragma unroll
        for (int r = 0; r < 4; r++) {
            int idx = r*128 + tid;
            int d = idx >> 3, cc = (idx & 7) * 8;
            *(uint4*)&Ks[d*QSTR + cc] = *(const uint4*)&kp[(size_t)d*HW_ + j0 + cc];
            *(uint4*)&Vs[d*QSTR + cc] = *(const uint4*)&vp[(size_t)d*HW_ + j0 + cc];
        }
        __syncthreads();

        // S = Q K^T (q pre-scaled)
        float s[8][4];
        #pragma unroll
        for (int nt = 0; nt < 8; nt++)
            #pragma unroll
            for (int e = 0; e < 4; e++) s[nt][e] = 0.f;

        #pragma unroll
        for (int ks = 0; ks < 4; ks++) {
            int kk = ks*16 + (lane & 15);
            #pragma unroll
            for (int nt = 0; nt < 8; nt++) {
                uint32_t b[2];
                ldsm2t(b, sptr(&Ks[kk*QSTR + nt*8]));
                mma_bf16(s[nt], qf[ks], b);
            }
        }

        // online softmax (rows r0 = warp*16 + lane/4, r1 = r0+8)
        float rmax0 = -1e30f, rmax1 = -1e30f;
        #pragma unroll
        for (int nt = 0; nt < 8; nt++) {
            rmax0 = fmaxf(rmax0, fmaxf(s[nt][0], s[nt][1]));
            rmax1 = fmaxf(rmax1, fmaxf(s[nt][2], s[nt][3]));
        }
        #pragma unroll
        for (int off = 1; off < 4; off <<= 1) {
            rmax0 = fmaxf(rmax0, __shfl_xor_sync(0xffffffffu, rmax0, off));
            rmax1 = fmaxf(rmax1, __shfl_xor_sync(0xffffffffu, rmax1, off));
        }
        float mn0 = fmaxf(mx0, rmax0), mn1 = fmaxf(mx1, rmax1);
        float corr0 = __expf(mx0 - mn0), corr1 = __expf(mx1 - mn1);
        mx0 = mn0; mx1 = mn1;

        float rs0 = 0.f, rs1 = 0.f;
        #pragma unroll
        for (int nt = 0; nt < 8; nt++) {
            s[nt][0] = __expf(s[nt][0] - mn0);
            s[nt][1] = __expf(s[nt][1] - mn0);
            s[nt][2] = __expf(s[nt][2] - mn1);
            s[nt][3] = __expf(s[nt][3] - mn1);
            rs0 += s[nt][0] + s[nt][1];
            rs1 += s[nt][2] + s[nt][3];
        }
        #pragma unroll
        for (int off = 1; off < 4; off <<= 1) {
            rs0 += __shfl_xor_sync(0xffffffffu, rs0, off);
            rs1 += __shfl_xor_sync(0xffffffffu, rs1, off);
        }
        l0 = l0*corr0 + rs0;
        l1 = l1*corr1 + rs1;
        #pragma unroll
        for (int nt = 0; nt < 8; nt++) {
            o[nt][0] *= corr0; o[nt][1] *= corr0;
            o[nt][2] *= corr1; o[nt][3] *= corr1;
        }

        // write P (bf16) — warp-private rows, warp sync only
        {
            int r0 = warp*16 + (lane >> 2);
            #pragma unroll
            for (int nt = 0; nt < 8; nt++) {
                int colj = nt*8 + 2*(lane & 3);
                *(uint32_t*)&Ps[r0*QSTR + colj]     = packbf(s[nt][0], s[nt][1]);
                *(uint32_t*)&Ps[(r0+8)*QSTR + colj] = packbf(s[nt][2], s[nt][3]);
            }
        }
        __syncwarp();

        // O += P @ V
        #pragma unroll
        for (int ks = 0; ks < 4; ks++) {
            uint32_t pa[4];
            {
                int g = lane >> 3;
                int row = warp*16 + (g & 1)*8 + (lane & 7);
                int col = ks*16 + (g >> 1)*8;
                ldsm4(pa, sptr(&Ps[row*QSTR + col]));
            }
            int jc = ks*16 + ((lane & 15) >> 3)*8;
            #pragma unroll
            for (int nt = 0; nt < 8; nt++) {
                uint32_t b[2];
                int dr = nt*8 + (lane & 7);
                ldsm2(b, sptr(&Vs[dr*QSTR + jc]));
                mma_bf16(o[nt], pa, b);
            }
        }
    }

    __syncthreads();   // everyone done with Ps before reuse as O stage
    // normalize + stage O as bf16 [d][i] into Ps
    {
        float inv0 = 1.f / l0, inv1 = 1.f / l1;
        int iq = warp*16 + (lane >> 2);
        __nv_bfloat16* Od = (__nv_bfloat16*)Ps;
        #pragma unroll
        for (int nt = 0; nt < 8; nt++) {
            int d = nt*8 + 2*(lane & 3);
            Od[(size_t)d*QSTR + iq]         = __float2bfloat16_rn(o[nt][0]*inv0);
            Od[(size_t)(d+1)*QSTR + iq]     = __float2bfloat16_rn(o[nt][1]*inv0);
            Od[(size_t)d*QSTR + iq + 8]     = __float2bfloat16_rn(o[nt][2]*inv1);
            Od[(size_t)(d+1)*QSTR + iq + 8] = __float2bfloat16_rn(o[nt][3]*inv1);
        }
    }
    __syncthreads();

    // coalesced store out[d][i]
    __nv_bfloat16* ob = outp + ((size_t)bb*CH + hh*HD) * HW_;
    #pragma unroll
    for (int r = 0; r < 4; r++) {
        int idx = r*128 + tid;
        int d = idx >> 3, cc = (idx & 7) * 8;
        *(uint4*)&ob[(size_t)d*HW_ + i0 + cc] = *(const uint4*)&Ps[d*QSTR + cc];
    }
}

// ---------------------------------------------------------------------------
extern "C" void kernel_launch(void* const* d_in, const int* in_sizes, int n_in,
                              void* d_out, int out_size)
{
    const float* x      = (const float*)d_in[0];
    const float* gn_w   = (const float*)d_in[1];
    const float* gn_b   = (const float*)d_in[2];
    const float* qkv_w  = (const float*)d_in[3];
    const float* qkv_b  = (const float*)d_in[4];
    const float* proj_w = (const float*)d_in[5];
    const float* proj_b = (const float*)d_in[6];
    float* out = (float*)d_out;

    __nv_bfloat16 *xn, *qkvb, *att;
    cudaGetSymbolAddress((void**)&xn,   g_xn);
    cudaGetSymbolAddress((void**)&qkvb, g_qkv);
    cudaGetSymbolAddress((void**)&att,  g_att);

    // 1) GroupNorm -> bf16
    groupnorm_kernel<<<BATCH*NGROUPS, 256>>>(x, gn_w, gn_b, xn);

    // 2) qkv GEMM (bf16 out, q rows pre-scaled by 1/8)
    mma_gemm_kernel<true><<<dim3(HW_/GBN, (3*CH)/GBM, BATCH), 256>>>(
        qkv_w, xn, qkvb, qkv_b, (const float*)0, 3*CH, CH, HW_, CH);

    // 3) fused flash attention (bf16 in/out)
    attention_kernel<<<dim3(HW_/64, BATCH*NH), 128>>>(qkvb, att);

    // 4) proj GEMM (fp32 out + bias + residual)
    mma_gemm_kernel<false><<<dim3(HW_/GBN, CH/GBM, BATCH), 256>>>(
        proj_w, att, out, proj_b, x, CH, CH, HW_, 0);
}

// round 9
// speedup vs baseline: 2.6514x; 1.2120x over previous
#include <cuda_runtime.h>
#include <cuda_bf16.h>
#include <math.h>
#include <stdint.h>

#define BATCH   16
#define CH      512
#define HW_     1024
#define NGROUPS 8
#define CG      64
#define NH      8
#define HD      64
#define EPS_    1e-5f
#define SCALE_  0.125f

// Scratch (allocation-free)
__device__ __nv_bfloat16 g_xn [BATCH*CH*HW_];
__device__ __nv_bfloat16 g_qkv[(size_t)BATCH*3*CH*HW_];
__device__ __nv_bfloat16 g_att[BATCH*CH*HW_];
__device__ __nv_bfloat16 g_wq [3*CH*CH];
__device__ __nv_bfloat16 g_wp [CH*CH];

// ---------------------------------------------------------------------------
// helpers
// ---------------------------------------------------------------------------
__device__ __forceinline__ uint32_t sptr(const void* p) {
    return (uint32_t)__cvta_generic_to_shared(p);
}
__device__ __forceinline__ uint32_t packbf(float a, float b) {
    __nv_bfloat162 t = __float22bfloat162_rn(make_float2(a, b));
    return *(uint32_t*)&t;
}
__device__ __forceinline__ void cpa16(uint32_t s, const void* g) {
    asm volatile("cp.async.cg.shared.global [%0],[%1],16;" :: "r"(s), "l"(g));
}
#define CP_COMMIT() asm volatile("cp.async.commit_group;")
#define CP_WAIT(n)  asm volatile("cp.async.wait_group %0;" :: "n"(n))

__device__ __forceinline__ void ldsm4(uint32_t* r, uint32_t a) {
    asm volatile("ldmatrix.sync.aligned.m8n8.x4.shared.b16 {%0,%1,%2,%3},[%4];"
        : "=r"(r[0]), "=r"(r[1]), "=r"(r[2]), "=r"(r[3]) : "r"(a));
}
__device__ __forceinline__ void ldsm4t(uint32_t* r, uint32_t a) {
    asm volatile("ldmatrix.sync.aligned.m8n8.x4.trans.shared.b16 {%0,%1,%2,%3},[%4];"
        : "=r"(r[0]), "=r"(r[1]), "=r"(r[2]), "=r"(r[3]) : "r"(a));
}
__device__ __forceinline__ void mma_bf16(float* c, const uint32_t* a, const uint32_t* b) {
    asm volatile("mma.sync.aligned.m16n8k16.row.col.f32.bf16.bf16.f32 "
        "{%0,%1,%2,%3},{%4,%5,%6,%7},{%8,%9},{%0,%1,%2,%3};"
        : "+f"(c[0]), "+f"(c[1]), "+f"(c[2]), "+f"(c[3])
        : "r"(a[0]), "r"(a[1]), "r"(a[2]), "r"(a[3]), "r"(b[0]), "r"(b[1]));
}

// ---------------------------------------------------------------------------
// fp32 -> bf16 weight conversion (runs once per launch; ~1MB)
// ---------------------------------------------------------------------------
__global__ void f2bf_kernel(const float* __restrict__ src,
                            __nv_bfloat16* __restrict__ dst, int n)
{
    int i = (blockIdx.x*blockDim.x + threadIdx.x) * 4;
    if (i < n) {
        float4 v = *(const float4*)&src[i];
        uint2 o;
        o.x = packbf(v.x, v.y);
        o.y = packbf(v.z, v.w);
        *(uint2*)&dst[i] = o;
    }
}

// ---------------------------------------------------------------------------
// GroupNorm -> bf16 (1024 threads)
// ---------------------------------------------------------------------------
__global__ void groupnorm_kernel(const float* __restrict__ x,
                                 const float* __restrict__ w,
                                 const float* __restrict__ bias,
                                 __nv_bfloat16* __restrict__ xn)
{
    int bg = blockIdx.x;
    int bb = bg / NGROUPS, g = bg % NGROUPS;
    const float*   xp = x  + ((size_t)bb*CH + g*CG) * HW_;
    __nv_bfloat16* op = xn + ((size_t)bb*CH + g*CG) * HW_;
    const int NEL = CG * HW_;
    int tid = threadIdx.x;

    float s = 0.f, ss = 0.f;
    for (int i = tid*4; i < NEL; i += blockDim.x*4) {
        float4 v = *(const float4*)&xp[i];
        s  += v.x + v.y + v.z + v.w;
        ss += v.x*v.x + v.y*v.y + v.z*v.z + v.w*v.w;
    }
    __shared__ float r1[1024], r2[1024];
    r1[tid] = s; r2[tid] = ss;
    __syncthreads();
    for (int st = 512; st > 0; st >>= 1) {
        if (tid < st) { r1[tid] += r1[tid+st]; r2[tid] += r2[tid+st]; }
        __syncthreads();
    }
    float mean = r1[0] * (1.f/NEL);
    float var  = r2[0] * (1.f/NEL) - mean*mean;
    float inv  = rsqrtf(var + EPS_);

    for (int i = tid*4; i < NEL; i += blockDim.x*4) {
        int ch = g*CG + (i >> 10);
        float wc = w[ch], bc = bias[ch];
        float4 v = *(const float4*)&xp[i];
        uint2 o;
        o.x = packbf((v.x - mean)*inv*wc + bc, (v.y - mean)*inv*wc + bc);
        o.y = packbf((v.z - mean)*inv*wc + bc, (v.w - mean)*inv*wc + bc);
        *(uint2*)&op[i] = o;
    }
}

// ---------------------------------------------------------------------------
// bf16 MMA GEMM: C[bz] = A[MxK](bf16) * B[bz][KxN](bf16) + bias
// 128x128x32, 8 warps (2x4), warp 64x32, cp.async double-buffered.
// ---------------------------------------------------------------------------
#define GBM 128
#define GBN 128
#define GBK 32
#define ASTR 40
#define BSTR 136

template<bool OUT_BF16>
__global__ __launch_bounds__(256)
void mma_gemm_kernel(const __nv_bfloat16* __restrict__ A,
                     const __nv_bfloat16* __restrict__ Bbase,
                     void* __restrict__ Cbase,
                     const float* __restrict__ bias,
                     const float* __restrict__ Rbase,
                     int M, int K, int N, int q_rows)
{
    __shared__ __align__(16) uint16_t As[2][GBM*ASTR];
    __shared__ __align__(16) uint16_t Bs[2][GBK*BSTR];

    int bz = blockIdx.z;
    const __nv_bfloat16* Bm = Bbase + (size_t)bz * K * N;

    int m0 = blockIdx.y * GBM, n0 = blockIdx.x * GBN;
    int tid = threadIdx.x, lane = tid & 31, warp = tid >> 5;
    int wm = (warp >> 2) * 64, wn = (warp & 3) * 32;

    int arow = tid >> 1, acol = (tid & 1) * 16;
    int brow = tid >> 3, bcol = (tid & 7) * 16;

    const __nv_bfloat16* Ab = A + (size_t)(m0 + arow)*K + acol;
    const __nv_bfloat16* Bb = Bm + (size_t)brow*N + n0 + bcol;

    float c[4][4][4];
    #pragma unroll
    for (int mt = 0; mt < 4; mt++)
        #pragma unroll
        for (int nt = 0; nt < 4; nt++)
            #pragma unroll
            for (int e = 0; e < 4; e++) c[mt][nt][e] = 0.f;

    // issue tile 0
    {
        cpa16(sptr(&As[0][arow*ASTR + acol]),     Ab);
        cpa16(sptr(&As[0][arow*ASTR + acol + 8]), Ab + 8);
        cpa16(sptr(&Bs[0][brow*BSTR + bcol]),     Bb);
        cpa16(sptr(&Bs[0][brow*BSTR + bcol + 8]), Bb + 8);
        CP_COMMIT();
    }

    const int KT = K / GBK;
    for (int kt = 0; kt < KT; kt++) {
        int buf = kt & 1;
        if (kt + 1 < KT) {
            int nb = (kt + 1) & 1;
            int k0 = (kt + 1) * GBK;
            cpa16(sptr(&As[nb][arow*ASTR + acol]),     Ab + k0);
            cpa16(sptr(&As[nb][arow*ASTR + acol + 8]), Ab + k0 + 8);
            cpa16(sptr(&Bs[nb][brow*BSTR + bcol]),     Bb + (size_t)k0*N);
            cpa16(sptr(&Bs[nb][brow*BSTR + bcol + 8]), Bb + (size_t)k0*N + 8);
            CP_COMMIT();
            CP_WAIT(1);
        } else {
            CP_WAIT(0);
        }
        __syncthreads();

        #pragma unroll
        for (int ks = 0; ks < 2; ks++) {
            uint32_t a[4][4], b[2][4];
            int g = lane >> 3;
            #pragma unroll
            for (int mt = 0; mt < 4; mt++) {
                int row = wm + mt*16 + (g & 1)*8 + (lane & 7);
                int col = ks*16 + (g >> 1)*8;
                ldsm4(a[mt], sptr(&As[buf][row*ASTR + col]));
            }
            int kk = ks*16 + (lane & 15);
            int cb = (lane >> 4)*8;
            ldsm4t(b[0], sptr(&Bs[buf][kk*BSTR + wn + cb]));
            ldsm4t(b[1], sptr(&Bs[buf][kk*BSTR + wn + 16 + cb]));
            #pragma unroll
            for (int mt = 0; mt < 4; mt++)
                #pragma unroll
                for (int ntp = 0; ntp < 2; ntp++) {
                    mma_bf16(c[mt][2*ntp],   a[mt], &b[ntp][0]);
                    mma_bf16(c[mt][2*ntp+1], a[mt], &b[ntp][2]);
                }
        }
        __syncthreads();
    }

    #pragma unroll
    for (int mt = 0; mt < 4; mt++) {
        #pragma unroll
        for (int half = 0; half < 2; half++) {
            int m = m0 + wm + mt*16 + (lane >> 2) + half*8;
            float bv = bias ? bias[m] : 0.f;
            #pragma unroll
            for (int nt = 0; nt < 4; nt++) {
                int n = n0 + wn + nt*8 + 2*(lane & 3);
                float x0 = c[mt][nt][half*2 + 0] + bv;
                float x1 = c[mt][nt][half*2 + 1] + bv;
                if (OUT_BF16) {
                    float sc = (m < q_rows) ? SCALE_ : 1.0f;
                    *(uint32_t*)((__nv_bfloat16*)Cbase + (size_t)bz*M*N + (size_t)m*N + n)
                        = packbf(x0*sc, x1*sc);
                } else {
                    float2 o = make_float2(x0, x1);
                    if (Rbase) {
                        float2 r = *(const float2*)&Rbase[(size_t)bz*M*N + (size_t)m*N + n];
                        o.x += r.x; o.y += r.y;
                    }
                    *(float2*)((float*)Cbase + (size_t)bz*M*N + (size_t)m*N + n) = o;
                }
            }
        }
    }
}

// ---------------------------------------------------------------------------
// Flash attention: 128 queries/block (2 q-tiles share K/V frags), 4 warps,
// cp.async double-buffered K/V, bf16 MMA. Q pre-scaled by 1/8.
// ---------------------------------------------------------------------------
#define KSTR 72    // K/V/P smem stride (halves)
#define QSTR2 136  // Q and O-stage stride (halves)

// dynamic smem layout (halves):
//   Qs : 64*136            = 8704
//   Ks : 2 * 64*72         = 9216
//   Vs : 2 * 64*72         = 9216
//   Ps : 128*72            = 9216   (reused as O stage 64*136=8704)
#define OFF_QS 0
#define OFF_KS (OFF_QS + 64*QSTR2)
#define OFF_VS (OFF_KS + 2*64*KSTR)
#define OFF_PS (OFF_VS + 2*64*KSTR)
#define ATT_SMEM_HALVES (OFF_PS + 128*KSTR)

__global__ __launch_bounds__(128)
void attention_kernel(const __nv_bfloat16* __restrict__ qkv,
                      __nv_bfloat16* __restrict__ outp)
{
    extern __shared__ __align__(16) uint16_t sm[];
    uint16_t* Qs = sm + OFF_QS;
    uint16_t* Ks = sm + OFF_KS;   // [2][64][72]
    uint16_t* Vs = sm + OFF_VS;
    uint16_t* Ps = sm + OFF_PS;   // [128][72]

    int bh = blockIdx.y;
    int bb = bh >> 3, hh = bh & 7;
    int i0 = blockIdx.x * 128;
    const __nv_bfloat16* qp = qkv + ((size_t)bb*3*CH + hh*HD) * HW_;
    const __nv_bfloat16* kp = qp + (size_t)CH * HW_;
    const __nv_bfloat16* vp = qp + (size_t)2*CH * HW_;

    int tid = threadIdx.x, lane = tid & 31, warp = tid >> 5;

    // issue Q (64x128) + KV tile 0 (64x64 each) via cp.async
    #pragma unroll
    for (int r = 0; r < 8; r++) {
        int idx = r*128 + tid;
        int d = idx >> 4, cc = (idx & 15) * 8;
        cpa16(sptr(&Qs[d*QSTR2 + cc]), qp + (size_t)d*HW_ + i0 + cc);
    }
    #pragma unroll
    for (int r = 0; r < 4; r++) {
        int idx = r*128 + tid;
        int d = idx >> 3, cc = (idx & 7) * 8;
        cpa16(sptr(&Ks[d*KSTR + cc]), kp + (size_t)d*HW_ + cc);
        cpa16(sptr(&Vs[d*KSTR + cc]), vp + (size_t)d*HW_ + cc);
    }
    CP_COMMIT();
    CP_WAIT(0);
    __syncthreads();

    // register-resident Q fragments for both q-tiles
    uint32_t qf[2][4][4];
    {
        int g = lane >> 3;
        int kq = (g >> 1)*8 + (lane & 7);
        #pragma unroll
        for (int t = 0; t < 2; t++) {
            int mq = t*64 + warp*16 + (g & 1)*8;
            #pragma unroll
            for (int ks = 0; ks < 4; ks++)
                ldsm4t(qf[t][ks], sptr(&Qs[(ks*16 + kq)*QSTR2 + mq]));
        }
    }

    float mx[2][2], l[2][2];
    float o[2][8][4];
    #pragma unroll
    for (int t = 0; t < 2; t++) {
        mx[t][0] = mx[t][1] = -1e30f;
        l[t][0] = l[t][1] = 0.f;
        #pragma unroll
        for (int nt = 0; nt < 8; nt++)
            #pragma unroll
            for (int e = 0; e < 4; e++) o[t][nt][e] = 0.f;
    }

    for (int jt = 0; jt < 16; jt++) {
        int cur = jt & 1;
        if (jt + 1 < 16) {
            int nb = (jt + 1) & 1;
            int j0 = (jt + 1) * 64;
            #pragma unroll
            for (int r = 0; r < 4; r++) {
                int idx = r*128 + tid;
                int d = idx >> 3, cc = (idx & 7) * 8;
                cpa16(sptr(&Ks[nb*64*KSTR + d*KSTR + cc]), kp + (size_t)d*HW_ + j0 + cc);
                cpa16(sptr(&Vs[nb*64*KSTR + d*KSTR + cc]), vp + (size_t)d*HW_ + j0 + cc);
            }
            CP_COMMIT();
            CP_WAIT(1);
        } else {
            CP_WAIT(0);
        }
        __syncthreads();

        const uint16_t* Kc = Ks + cur*64*KSTR;
        const uint16_t* Vc = Vs + cur*64*KSTR;

        // S = Q K^T for both q-tiles, sharing K frags
        float s[2][8][4];
        #pragma unroll
        for (int t = 0; t < 2; t++)
            #pragma unroll
            for (int nt = 0; nt < 8; nt++)
                #pragma unroll
                for (int e = 0; e < 4; e++) s[t][nt][e] = 0.f;

        #pragma unroll
        for (int ks = 0; ks < 4; ks++) {
            int kk = ks*16 + (lane & 15);
            int cb = (lane >> 4)*8;
            #pragma unroll
            for (int ntp = 0; ntp < 4; ntp++) {
                uint32_t b[4];
                ldsm4t(b, sptr(&Kc[kk*KSTR + ntp*16 + cb]));
                #pragma unroll
                for (int t = 0; t < 2; t++) {
                    mma_bf16(s[t][2*ntp],   qf[t][ks], &b[0]);
                    mma_bf16(s[t][2*ntp+1], qf[t][ks], &b[2]);
                }
            }
        }

        // online softmax per q-tile
        #pragma unroll
        for (int t = 0; t < 2; t++) {
            float rmax0 = -1e30f, rmax1 = -1e30f;
            #pragma unroll
            for (int nt = 0; nt < 8; nt++) {
                rmax0 = fmaxf(rmax0, fmaxf(s[t][nt][0], s[t][nt][1]));
                rmax1 = fmaxf(rmax1, fmaxf(s[t][nt][2], s[t][nt][3]));
            }
            #pragma unroll
            for (int off = 1; off < 4; off <<= 1) {
                rmax0 = fmaxf(rmax0, __shfl_xor_sync(0xffffffffu, rmax0, off));
                rmax1 = fmaxf(rmax1, __shfl_xor_sync(0xffffffffu, rmax1, off));
            }
            float mn0 = fmaxf(mx[t][0], rmax0), mn1 = fmaxf(mx[t][1], rmax1);
            float corr0 = __expf(mx[t][0] - mn0), corr1 = __expf(mx[t][1] - mn1);
            mx[t][0] = mn0; mx[t][1] = mn1;

            float rs0 = 0.f, rs1 = 0.f;
            #pragma unroll
            for (int nt = 0; nt < 8; nt++) {
                s[t][nt][0] = __expf(s[t][nt][0] - mn0);
                s[t][nt][1] = __expf(s[t][nt][1] - mn0);
                s[t][nt][2] = __expf(s[t][nt][2] - mn1);
                s[t][nt][3] = __expf(s[t][nt][3] - mn1);
                rs0 += s[t][nt][0] + s[t][nt][1];
                rs1 += s[t][nt][2] + s[t][nt][3];
            }
            #pragma unroll
            for (int off = 1; off < 4; off <<= 1) {
                rs0 += __shfl_xor_sync(0xffffffffu, rs0, off);
                rs1 += __shfl_xor_sync(0xffffffffu, rs1, off);
            }
            l[t][0] = l[t][0]*corr0 + rs0;
            l[t][1] = l[t][1]*corr1 + rs1;
            #pragma unroll
            for (int nt = 0; nt < 8; nt++) {
                o[t][nt][0] *= corr0; o[t][nt][1] *= corr0;
                o[t][nt][2] *= corr1; o[t][nt][3] *= corr1;
            }

            // write P rows for this q-tile (warp-private rows)
            int r0 = t*64 + warp*16 + (lane >> 2);
            #pragma unroll
            for (int nt = 0; nt < 8; nt++) {
                int colj = nt*8 + 2*(lane & 3);
                *(uint32_t*)&Ps[r0*KSTR + colj]     = packbf(s[t][nt][0], s[t][nt][1]);
                *(uint32_t*)&Ps[(r0+8)*KSTR + colj] = packbf(s[t][nt][2], s[t][nt][3]);
            }
        }
        __syncwarp();

        // O += P @ V, sharing V frags across q-tiles
        #pragma unroll
        for (int ks = 0; ks < 4; ks++) {
            uint32_t pa[2][4];
            int g = lane >> 3;
            int col = ks*16 + (g >> 1)*8;
            #pragma unroll
            for (int t = 0; t < 2; t++) {
                int row = t*64 + warp*16 + (g & 1)*8 + (lane & 7);
                ldsm4(pa[t], sptr(&Ps[row*KSTR + col]));
            }
            int jc = ks*16 + ((lane >> 3) & 1)*8;
            int dbase = (lane >> 4)*8 + (lane & 7);
            #pragma unroll
            for (int ntp = 0; ntp < 4; ntp++) {
                uint32_t b[4];
                ldsm4(b, sptr(&Vc[(ntp*16 + dbase)*KSTR + jc]));
                #pragma unroll
                for (int t = 0; t < 2; t++) {
                    mma_bf16(o[t][2*ntp],   pa[t], &b[0]);
                    mma_bf16(o[t][2*ntp+1], pa[t], &b[2]);
                }
            }
        }
        __syncthreads();
    }

    // normalize + stage O as bf16 [d][i] into Ps
    {
        __nv_bfloat16* Od = (__nv_bfloat16*)Ps;
        #pragma unroll
        for (int t = 0; t < 2; t++) {
            float inv0 = 1.f / l[t][0], inv1 = 1.f / l[t][1];
            int iq = t*64 + warp*16 + (lane >> 2);
            #pragma unroll
            for (int nt = 0; nt < 8; nt++) {
                int d = nt*8 + 2*(lane & 3);
                Od[(size_t)d*QSTR2 + iq]         = __float2bfloat16_rn(o[t][nt][0]*inv0);
                Od[(size_t)(d+1)*QSTR2 + iq]     = __float2bfloat16_rn(o[t][nt][1]*inv0);
                Od[(size_t)d*QSTR2 + iq + 8]     = __float2bfloat16_rn(o[t][nt][2]*inv1);
                Od[(size_t)(d+1)*QSTR2 + iq + 8] = __float2bfloat16_rn(o[t][nt][3]*inv1);
            }
        }
    }
    __syncthreads();

    // coalesced store out[d][i0..i0+127]
    __nv_bfloat16* ob = outp + ((size_t)bb*CH + hh*HD) * HW_;
    #pragma unroll
    for (int r = 0; r < 8; r++) {
        int idx = r*128 + tid;
        int d = idx >> 4, cc = (idx & 15) * 8;
        *(uint4*)&ob[(size_t)d*HW_ + i0 + cc] = *(const uint4*)&Ps[d*QSTR2 + cc];
    }
}

// ---------------------------------------------------------------------------
extern "C" void kernel_launch(void* const* d_in, const int* in_sizes, int n_in,
                              void* d_out, int out_size)
{
    const float* x      = (const float*)d_in[0];
    const float* gn_w   = (const float*)d_in[1];
    const float* gn_b   = (const float*)d_in[2];
    const float* qkv_w  = (const float*)d_in[3];
    const float* qkv_b  = (const float*)d_in[4];
    const float* proj_w = (const float*)d_in[5];
    const float* proj_b = (const float*)d_in[6];
    float* out = (float*)d_out;

    __nv_bfloat16 *xn, *qkvb, *att, *wq, *wp;
    cudaGetSymbolAddress((void**)&xn,   g_xn);
    cudaGetSymbolAddress((void**)&qkvb, g_qkv);
    cudaGetSymbolAddress((void**)&att,  g_att);
    cudaGetSymbolAddress((void**)&wq,   g_wq);
    cudaGetSymbolAddress((void**)&wp,   g_wp);

    const int ATT_SMEM = ATT_SMEM_HALVES * 2;   // bytes (~73KB)
    cudaFuncSetAttribute(attention_kernel,
                         cudaFuncAttributeMaxDynamicSharedMemorySize, ATT_SMEM);

    // 0) weights fp32 -> bf16
    f2bf_kernel<<<(3*CH*CH/4 + 255)/256, 256>>>(qkv_w, wq, 3*CH*CH);
    f2bf_kernel<<<(CH*CH/4 + 255)/256, 256>>>(proj_w, wp, CH*CH);

    // 1) GroupNorm -> bf16
    groupnorm_kernel<<<BATCH*NGROUPS, 1024>>>(x, gn_w, gn_b, xn);

    // 2) qkv GEMM (bf16 out, q rows pre-scaled)
    mma_gemm_kernel<true><<<dim3(HW_/GBN, (3*CH)/GBM, BATCH), 256>>>(
        wq, xn, qkvb, qkv_b, (const float*)0, 3*CH, CH, HW_, CH);

    // 3) flash attention (128 queries/block)
    attention_kernel<<<dim3(HW_/128, BATCH*NH), 128, ATT_SMEM>>>(qkvb, att);

    // 4) proj GEMM (fp32 out + bias + residual)
    mma_gemm_kernel<false><<<dim3(HW_/GBN, CH/GBM, BATCH), 256>>>(
        wp, att, out, proj_b, x, CH, CH, HW_, 0);
}

// round 10
// speedup vs baseline: 2.8063x; 1.0584x over previous
#include <cuda_runtime.h>
#include <cuda_bf16.h>
#include <math.h>
#include <stdint.h>

#define BATCH   16
#define CH      512
#define HW_     1024
#define NGROUPS 8
#define CG      64
#define NH      8
#define HD      64
#define EPS_    1e-5f
#define SCALE_  0.125f

// Scratch (allocation-free)
__device__ __nv_bfloat16 g_xn [BATCH*CH*HW_];
__device__ __nv_bfloat16 g_qkv[(size_t)BATCH*3*CH*HW_];
__device__ __nv_bfloat16 g_att[BATCH*CH*HW_];
__device__ __nv_bfloat16 g_wq [3*CH*CH];
__device__ __nv_bfloat16 g_wp [CH*CH];

// ---------------------------------------------------------------------------
// helpers
// ---------------------------------------------------------------------------
__device__ __forceinline__ uint32_t sptr(const void* p) {
    return (uint32_t)__cvta_generic_to_shared(p);
}
__device__ __forceinline__ uint32_t packbf(float a, float b) {
    __nv_bfloat162 t = __float22bfloat162_rn(make_float2(a, b));
    return *(uint32_t*)&t;
}
__device__ __forceinline__ void cpa16(uint32_t s, const void* g) {
    asm volatile("cp.async.cg.shared.global [%0],[%1],16;" :: "r"(s), "l"(g));
}
#define CP_COMMIT() asm volatile("cp.async.commit_group;")
#define CP_WAIT(n)  asm volatile("cp.async.wait_group %0;" :: "n"(n))

__device__ __forceinline__ void ldsm4(uint32_t* r, uint32_t a) {
    asm volatile("ldmatrix.sync.aligned.m8n8.x4.shared.b16 {%0,%1,%2,%3},[%4];"
        : "=r"(r[0]), "=r"(r[1]), "=r"(r[2]), "=r"(r[3]) : "r"(a));
}
__device__ __forceinline__ void ldsm4t(uint32_t* r, uint32_t a) {
    asm volatile("ldmatrix.sync.aligned.m8n8.x4.trans.shared.b16 {%0,%1,%2,%3},[%4];"
        : "=r"(r[0]), "=r"(r[1]), "=r"(r[2]), "=r"(r[3]) : "r"(a));
}
__device__ __forceinline__ void mma_bf16(float* c, const uint32_t* a, const uint32_t* b) {
    asm volatile("mma.sync.aligned.m16n8k16.row.col.f32.bf16.bf16.f32 "
        "{%0,%1,%2,%3},{%4,%5,%6,%7},{%8,%9},{%0,%1,%2,%3};"
        : "+f"(c[0]), "+f"(c[1]), "+f"(c[2]), "+f"(c[3])
        : "r"(a[0]), "r"(a[1]), "r"(a[2]), "r"(a[3]), "r"(b[0]), "r"(b[1]));
}

// ---------------------------------------------------------------------------
// fp32 -> bf16 weight conversion
// ---------------------------------------------------------------------------
__global__ void f2bf_kernel(const float* __restrict__ src,
                            __nv_bfloat16* __restrict__ dst, int n)
{
    int i = (blockIdx.x*blockDim.x + threadIdx.x) * 4;
    if (i < n) {
        float4 v = *(const float4*)&src[i];
        uint2 o;
        o.x = packbf(v.x, v.y);
        o.y = packbf(v.z, v.w);
        *(uint2*)&dst[i] = o;
    }
}

// ---------------------------------------------------------------------------
// GroupNorm -> bf16
// ---------------------------------------------------------------------------
__global__ void groupnorm_kernel(const float* __restrict__ x,
                                 const float* __restrict__ w,
                                 const float* __restrict__ bias,
                                 __nv_bfloat16* __restrict__ xn)
{
    int bg = blockIdx.x;
    int bb = bg / NGROUPS, g = bg % NGROUPS;
    const float*   xp = x  + ((size_t)bb*CH + g*CG) * HW_;
    __nv_bfloat16* op = xn + ((size_t)bb*CH + g*CG) * HW_;
    const int NEL = CG * HW_;
    int tid = threadIdx.x;

    float s = 0.f, ss = 0.f;
    for (int i = tid*4; i < NEL; i += blockDim.x*4) {
        float4 v = *(const float4*)&xp[i];
        s  += v.x + v.y + v.z + v.w;
        ss += v.x*v.x + v.y*v.y + v.z*v.z + v.w*v.w;
    }
    __shared__ float r1[1024], r2[1024];
    r1[tid] = s; r2[tid] = ss;
    __syncthreads();
    for (int st = 512; st > 0; st >>= 1) {
        if (tid < st) { r1[tid] += r1[tid+st]; r2[tid] += r2[tid+st]; }
        __syncthreads();
    }
    float mean = r1[0] * (1.f/NEL);
    float var  = r2[0] * (1.f/NEL) - mean*mean;
    float inv  = rsqrtf(var + EPS_);

    for (int i = tid*4; i < NEL; i += blockDim.x*4) {
        int ch = g*CG + (i >> 10);
        float wc = w[ch], bc = bias[ch];
        float4 v = *(const float4*)&xp[i];
        uint2 o;
        o.x = packbf((v.x - mean)*inv*wc + bc, (v.y - mean)*inv*wc + bc);
        o.y = packbf((v.z - mean)*inv*wc + bc, (v.w - mean)*inv*wc + bc);
        *(uint2*)&op[i] = o;
    }
}

// ---------------------------------------------------------------------------
// bf16 MMA GEMM, 4-stage cp.async pipeline, single sync per K-iteration.
// 128x128x32, 8 warps (2x4), warp 64x32.
// ---------------------------------------------------------------------------
#define GBM 128
#define GBN 128
#define GBK 32
#define ASTR 40
#define BSTR 136
#define A_ST (GBM*ASTR)
#define B_ST (GBK*BSTR)
#define GEMM_SMEM ((4*A_ST + 4*B_ST) * 2)   // 75776 B

template<bool OUT_BF16>
__global__ __launch_bounds__(256)
void mma_gemm_kernel(const __nv_bfloat16* __restrict__ A,
                     const __nv_bfloat16* __restrict__ Bbase,
                     void* __restrict__ Cbase,
                     const float* __restrict__ bias,
                     const float* __restrict__ Rbase,
                     int M, int K, int N, int q_rows)
{
    extern __shared__ __align__(16) uint16_t smg[];
    uint16_t* As = smg;              // [4][128*40]
    uint16_t* Bs = smg + 4*A_ST;     // [4][32*136]

    int bz = blockIdx.z;
    const __nv_bfloat16* Bm = Bbase + (size_t)bz * K * N;

    int m0 = blockIdx.y * GBM, n0 = blockIdx.x * GBN;
    int tid = threadIdx.x, lane = tid & 31, warp = tid >> 5;
    int wm = (warp >> 2) * 64, wn = (warp & 3) * 32;

    int arow = tid >> 1, acol = (tid & 1) * 16;
    int brow = tid >> 3, bcol = (tid & 7) * 16;

    const __nv_bfloat16* Ab = A + (size_t)(m0 + arow)*K + acol;
    const __nv_bfloat16* Bb = Bm + (size_t)brow*N + n0 + bcol;

    float c[4][4][4];
    #pragma unroll
    for (int mt = 0; mt < 4; mt++)
        #pragma unroll
        for (int nt = 0; nt < 4; nt++)
            #pragma unroll
            for (int e = 0; e < 4; e++) c[mt][nt][e] = 0.f;

    const int KT = K / GBK;

    // prologue: 3 stages in flight
    #pragma unroll
    for (int p = 0; p < 3; p++) {
        int st = p, k0 = p * GBK;
        cpa16(sptr(&As[st*A_ST + arow*ASTR + acol]),     Ab + k0);
        cpa16(sptr(&As[st*A_ST + arow*ASTR + acol + 8]), Ab + k0 + 8);
        cpa16(sptr(&Bs[st*B_ST + brow*BSTR + bcol]),     Bb + (size_t)k0*N);
        cpa16(sptr(&Bs[st*B_ST + brow*BSTR + bcol + 8]), Bb + (size_t)k0*N + 8);
        CP_COMMIT();
    }

    for (int kt = 0; kt < KT; kt++) {
        CP_WAIT(2);            // group kt complete (3+kt committed, <=2 pending)
        __syncthreads();

        const uint16_t* Ac = As + (kt & 3)*A_ST;
        const uint16_t* Bc = Bs + (kt & 3)*B_ST;

        #pragma unroll
        for (int ks = 0; ks < 2; ks++) {
            uint32_t a[4][4], b[2][4];
            int g = lane >> 3;
            #pragma unroll
            for (int mt = 0; mt < 4; mt++) {
                int row = wm + mt*16 + (g & 1)*8 + (lane & 7);
                int col = ks*16 + (g >> 1)*8;
                ldsm4(a[mt], sptr(&Ac[row*ASTR + col]));
            }
            int kk = ks*16 + (lane & 15);
            int cb = (lane >> 4)*8;
            ldsm4t(b[0], sptr(&Bc[kk*BSTR + wn + cb]));
            ldsm4t(b[1], sptr(&Bc[kk*BSTR + wn + 16 + cb]));
            #pragma unroll
            for (int mt = 0; mt < 4; mt++)
                #pragma unroll
                for (int ntp = 0; ntp < 2; ntp++) {
                    mma_bf16(c[mt][2*ntp],   a[mt], &b[ntp][0]);
                    mma_bf16(c[mt][2*ntp+1], a[mt], &b[ntp][2]);
                }
        }

        // issue stage kt+3 (writes buf (kt-1)%4: all warps finished reading it
        // before the sync above). Empty commit keeps group counting uniform.
        if (kt + 3 < KT) {
            int st = (kt + 3) & 3, k0 = (kt + 3) * GBK;
            cpa16(sptr(&As[st*A_ST + arow*ASTR + acol]),     Ab + k0);
            cpa16(sptr(&As[st*A_ST + arow*ASTR + acol + 8]), Ab + k0 + 8);
            cpa16(sptr(&Bs[st*B_ST + brow*BSTR + bcol]),     Bb + (size_t)k0*N);
            cpa16(sptr(&Bs[st*B_ST + brow*BSTR + bcol + 8]), Bb + (size_t)k0*N + 8);
        }
        CP_COMMIT();
    }

    #pragma unroll
    for (int mt = 0; mt < 4; mt++) {
        #pragma unroll
        for (int half = 0; half < 2; half++) {
            int m = m0 + wm + mt*16 + (lane >> 2) + half*8;
            float bv = bias ? bias[m] : 0.f;
            #pragma unroll
            for (int nt = 0; nt < 4; nt++) {
                int n = n0 + wn + nt*8 + 2*(lane & 3);
                float x0 = c[mt][nt][half*2 + 0] + bv;
                float x1 = c[mt][nt][half*2 + 1] + bv;
                if (OUT_BF16) {
                    float sc = (m < q_rows) ? SCALE_ : 1.0f;
                    *(uint32_t*)((__nv_bfloat16*)Cbase + (size_t)bz*M*N + (size_t)m*N + n)
                        = packbf(x0*sc, x1*sc);
                } else {
                    float2 o = make_float2(x0, x1);
                    if (Rbase) {
                        float2 r = *(const float2*)&Rbase[(size_t)bz*M*N + (size_t)m*N + n];
                        o.x += r.x; o.y += r.y;
                    }
                    *(float2*)((float*)Cbase + (size_t)bz*M*N + (size_t)m*N + n) = o;
                }
            }
        }
    }
}

// ---------------------------------------------------------------------------
// Flash attention: 128 queries/block, 4 warps, 3-stage cp.async KV pipeline,
// single sync per KV tile, P kept in registers (C-frag == A-frag identity).
// ---------------------------------------------------------------------------
#define KSTR 72
#define QSTR2 136
#define OFF_KS (64*QSTR2)                      // after Qs
#define OFF_VS (OFF_KS + 3*64*KSTR)
#define ATT_SMEM_HALVES (OFF_VS + 3*64*KSTR)   // 36352
#define ATT_SMEM (ATT_SMEM_HALVES * 2)         // 72704 B

__global__ __launch_bounds__(128)
void attention_kernel(const __nv_bfloat16* __restrict__ qkv,
                      __nv_bfloat16* __restrict__ outp)
{
    extern __shared__ __align__(16) uint16_t sm[];
    uint16_t* Qs = sm;            // [64][136] — Q stage, then O stage
    uint16_t* Ks = sm + OFF_KS;   // [3][64][72]
    uint16_t* Vs = sm + OFF_VS;   // [3][64][72]

    int bh = blockIdx.y;
    int bb = bh >> 3, hh = bh & 7;
    int i0 = blockIdx.x * 128;
    const __nv_bfloat16* qp = qkv + ((size_t)bb*3*CH + hh*HD) * HW_;
    const __nv_bfloat16* kp = qp + (size_t)CH * HW_;
    const __nv_bfloat16* vp = qp + (size_t)2*CH * HW_;

    int tid = threadIdx.x, lane = tid & 31, warp = tid >> 5;

    // prologue: group0 = Q + KV tile 0; group1 = KV tile 1
    #pragma unroll
    for (int r = 0; r < 8; r++) {
        int idx = r*128 + tid;
        int d = idx >> 4, cc = (idx & 15) * 8;
        cpa16(sptr(&Qs[d*QSTR2 + cc]), qp + (size_t)d*HW_ + i0 + cc);
    }
    #pragma unroll
    for (int r = 0; r < 4; r++) {
        int idx = r*128 + tid;
        int d = idx >> 3, cc = (idx & 7) * 8;
        cpa16(sptr(&Ks[d*KSTR + cc]), kp + (size_t)d*HW_ + cc);
        cpa16(sptr(&Vs[d*KSTR + cc]), vp + (size_t)d*HW_ + cc);
    }
    CP_COMMIT();
    #pragma unroll
    for (int r = 0; r < 4; r++) {
        int idx = r*128 + tid;
        int d = idx >> 3, cc = (idx & 7) * 8;
        cpa16(sptr(&Ks[64*KSTR + d*KSTR + cc]), kp + (size_t)d*HW_ + 64 + cc);
        cpa16(sptr(&Vs[64*KSTR + d*KSTR + cc]), vp + (size_t)d*HW_ + 64 + cc);
    }
    CP_COMMIT();

    uint32_t qf[2][4][4];
    float mx[2][2], l[2][2];
    float o[2][8][4];
    #pragma unroll
    for (int t = 0; t < 2; t++) {
        mx[t][0] = mx[t][1] = -1e30f;
        l[t][0] = l[t][1] = 0.f;
        #pragma unroll
        for (int nt = 0; nt < 8; nt++)
            #pragma unroll
            for (int e = 0; e < 4; e++) o[t][nt][e] = 0.f;
    }

    for (int jt = 0; jt < 16; jt++) {
        CP_WAIT(1);
        __syncthreads();

        if (jt == 0) {   // Q frags (register-resident afterwards)
            int g = lane >> 3;
            int kq = (g >> 1)*8 + (lane & 7);
            #pragma unroll
            for (int t = 0; t < 2; t++) {
                int mq = t*64 + warp*16 + (g & 1)*8;
                #pragma unroll
                for (int ks = 0; ks < 4; ks++)
                    ldsm4t(qf[t][ks], sptr(&Qs[(ks*16 + kq)*QSTR2 + mq]));
            }
        }

        const uint16_t* Kc = Ks + (jt % 3)*64*KSTR;
        const uint16_t* Vc = Vs + (jt % 3)*64*KSTR;

        // S = Q K^T (both q-tiles share K frags)
        float s[2][8][4];
        #pragma unroll
        for (int t = 0; t < 2; t++)
            #pragma unroll
            for (int nt = 0; nt < 8; nt++)
                #pragma unroll
                for (int e = 0; e < 4; e++) s[t][nt][e] = 0.f;

        #pragma unroll
        for (int ks = 0; ks < 4; ks++) {
            int kk = ks*16 + (lane & 15);
            int cb = (lane >> 4)*8;
            #pragma unroll
            for (int ntp = 0; ntp < 4; ntp++) {
                uint32_t b[4];
                ldsm4t(b, sptr(&Kc[kk*KSTR + ntp*16 + cb]));
                #pragma unroll
                for (int t = 0; t < 2; t++) {
                    mma_bf16(s[t][2*ntp],   qf[t][ks], &b[0]);
                    mma_bf16(s[t][2*ntp+1], qf[t][ks], &b[2]);
                }
            }
        }

        // online softmax per q-tile (rows r0 = lane>>2, r1 = r0+8)
        #pragma unroll
        for (int t = 0; t < 2; t++) {
            float rmax0 = -1e30f, rmax1 = -1e30f;
            #pragma unroll
            for (int nt = 0; nt < 8; nt++) {
                rmax0 = fmaxf(rmax0, fmaxf(s[t][nt][0], s[t][nt][1]));
                rmax1 = fmaxf(rmax1, fmaxf(s[t][nt][2], s[t][nt][3]));
            }
            #pragma unroll
            for (int off = 1; off < 4; off <<= 1) {
                rmax0 = fmaxf(rmax0, __shfl_xor_sync(0xffffffffu, rmax0, off));
                rmax1 = fmaxf(rmax1, __shfl_xor_sync(0xffffffffu, rmax1, off));
            }
            float mn0 = fmaxf(mx[t][0], rmax0), mn1 = fmaxf(mx[t][1], rmax1);
            float corr0 = __expf(mx[t][0] - mn0), corr1 = __expf(mx[t][1] - mn1);
            mx[t][0] = mn0; mx[t][1] = mn1;

            float rs0 = 0.f, rs1 = 0.f;
            #pragma unroll
            for (int nt = 0; nt < 8; nt++) {
                s[t][nt][0] = __expf(s[t][nt][0] - mn0);
                s[t][nt][1] = __expf(s[t][nt][1] - mn0);
                s[t][nt][2] = __expf(s[t][nt][2] - mn1);
                s[t][nt][3] = __expf(s[t][nt][3] - mn1);
                rs0 += s[t][nt][0] + s[t][nt][1];
                rs1 += s[t][nt][2] + s[t][nt][3];
            }
            #pragma unroll
            for (int off = 1; off < 4; off <<= 1) {
                rs0 += __shfl_xor_sync(0xffffffffu, rs0, off);
                rs1 += __shfl_xor_sync(0xffffffffu, rs1, off);
            }
            l[t][0] = l[t][0]*corr0 + rs0;
            l[t][1] = l[t][1]*corr1 + rs1;
            #pragma unroll
            for (int nt = 0; nt < 8; nt++) {
                o[t][nt][0] *= corr0; o[t][nt][1] *= corr0;
                o[t][nt][2] *= corr1; o[t][nt][3] *= corr1;
            }
        }

        // O += P @ V — P A-frags straight from S C-frags (no smem round-trip):
        // chunk ks (k=16ks..16ks+15): a0=pack(s[2ks][0,1]) a1=pack(s[2ks][2,3])
        //                             a2=pack(s[2ks+1][0,1]) a3=pack(s[2ks+1][2,3])
        #pragma unroll
        for (int ks = 0; ks < 4; ks++) {
            uint32_t pa[2][4];
            #pragma unroll
            for (int t = 0; t < 2; t++) {
                pa[t][0] = packbf(s[t][2*ks][0],   s[t][2*ks][1]);
                pa[t][1] = packbf(s[t][2*ks][2],   s[t][2*ks][3]);
                pa[t][2] = packbf(s[t][2*ks+1][0], s[t][2*ks+1][1]);
                pa[t][3] = packbf(s[t][2*ks+1][2], s[t][2*ks+1][3]);
            }
            int jc = ks*16 + ((lane >> 3) & 1)*8;
            int dbase = (lane >> 4)*8 + (lane & 7);
            #pragma unroll
            for (int ntp = 0; ntp < 4; ntp++) {
                uint32_t b[4];
                ldsm4(b, sptr(&Vc[(ntp*16 + dbase)*KSTR + jc]));
                #pragma unroll
                for (int t = 0; t < 2; t++) {
                    mma_bf16(o[t][2*ntp],   pa[t], &b[0]);
                    mma_bf16(o[t][2*ntp+1], pa[t], &b[2]);
                }
            }
        }

        // issue KV tile jt+2 (stage (jt-1)%3: all readers done before sync above)
        if (jt + 2 < 16) {
            int stp = (jt + 2) % 3;
            int j0 = (jt + 2) * 64;
            #pragma unroll
            for (int r = 0; r < 4; r++) {
                int idx = r*128 + tid;
                int d = idx >> 3, cc = (idx & 7) * 8;
                cpa16(sptr(&Ks[stp*64*KSTR + d*KSTR + cc]), kp + (size_t)d*HW_ + j0 + cc);
                cpa16(sptr(&Vs[stp*64*KSTR + d*KSTR + cc]), vp + (size_t)d*HW_ + j0 + cc);
            }
        }
        CP_COMMIT();
    }

    // normalize + stage O as bf16 [d][i] into Qs (Q long consumed)
    {
        __nv_bfloat16* Od = (__nv_bfloat16*)Qs;
        #pragma unroll
        for (int t = 0; t < 2; t++) {
            float inv0 = 1.f / l[t][0], inv1 = 1.f / l[t][1];
            int iq = t*64 + warp*16 + (lane >> 2);
            #pragma unroll
            for (int nt = 0; nt < 8; nt++) {
                int d = nt*8 + 2*(lane & 3);
                Od[(size_t)d*QSTR2 + iq]         = __float2bfloat16_rn(o[t][nt][0]*inv0);
                Od[(size_t)(d+1)*QSTR2 + iq]     = __float2bfloat16_rn(o[t][nt][1]*inv0);
                Od[(size_t)d*QSTR2 + iq + 8]     = __float2bfloat16_rn(o[t][nt][2]*inv1);
                Od[(size_t)(d+1)*QSTR2 + iq + 8] = __float2bfloat16_rn(o[t][nt][3]*inv1);
            }
        }
    }
    __syncthreads();

    // coalesced store out[d][i0..i0+127]
    __nv_bfloat16* ob = outp + ((size_t)bb*CH + hh*HD) * HW_;
    #pragma unroll
    for (int r = 0; r < 8; r++) {
        int idx = r*128 + tid;
        int d = idx >> 4, cc = (idx & 15) * 8;
        *(uint4*)&ob[(size_t)d*HW_ + i0 + cc] = *(const uint4*)&Qs[d*QSTR2 + cc];
    }
}

// ---------------------------------------------------------------------------
extern "C" void kernel_launch(void* const* d_in, const int* in_sizes, int n_in,
                              void* d_out, int out_size)
{
    const float* x      = (const float*)d_in[0];
    const float* gn_w   = (const float*)d_in[1];
    const float* gn_b   = (const float*)d_in[2];
    const float* qkv_w  = (const float*)d_in[3];
    const float* qkv_b  = (const float*)d_in[4];
    const float* proj_w = (const float*)d_in[5];
    const float* proj_b = (const float*)d_in[6];
    float* out = (float*)d_out;

    __nv_bfloat16 *xn, *qkvb, *att, *wq, *wp;
    cudaGetSymbolAddress((void**)&xn,   g_xn);
    cudaGetSymbolAddress((void**)&qkvb, g_qkv);
    cudaGetSymbolAddress((void**)&att,  g_att);
    cudaGetSymbolAddress((void**)&wq,   g_wq);
    cudaGetSymbolAddress((void**)&wp,   g_wp);

    cudaFuncSetAttribute(mma_gemm_kernel<true>,
                         cudaFuncAttributeMaxDynamicSharedMemorySize, GEMM_SMEM);
    cudaFuncSetAttribute(mma_gemm_kernel<false>,
                         cudaFuncAttributeMaxDynamicSharedMemorySize, GEMM_SMEM);
    cudaFuncSetAttribute(attention_kernel,
                         cudaFuncAttributeMaxDynamicSharedMemorySize, ATT_SMEM);

    // 0) weights fp32 -> bf16
    f2bf_kernel<<<(3*CH*CH/4 + 255)/256, 256>>>(qkv_w, wq, 3*CH*CH);
    f2bf_kernel<<<(CH*CH/4 + 255)/256, 256>>>(proj_w, wp, CH*CH);

    // 1) GroupNorm -> bf16
    groupnorm_kernel<<<BATCH*NGROUPS, 1024>>>(x, gn_w, gn_b, xn);

    // 2) qkv GEMM (bf16 out, q rows pre-scaled)
    mma_gemm_kernel<true><<<dim3(HW_/GBN, (3*CH)/GBM, BATCH), 256, GEMM_SMEM>>>(
        wq, xn, qkvb, qkv_b, (const float*)0, 3*CH, CH, HW_, CH);

    // 3) flash attention (128 queries/block)
    attention_kernel<<<dim3(HW_/128, BATCH*NH), 128, ATT_SMEM>>>(qkvb, att);

    // 4) proj GEMM (fp32 out + bias + residual)
    mma_gemm_kernel<false><<<dim3(HW_/GBN, CH/GBM, BATCH), 256, GEMM_SMEM>>>(
        wp, att, out, proj_b, x, CH, CH, HW_, 0);
}